// round 14
// baseline (speedup 1.0000x reference)
#include <cuda_runtime.h>
#include <cuda_fp16.h>
#include <math.h>
#include <stdint.h>

// ---------------- problem constants ----------------
#define NS   16384
#define FF   512
#define BBR  4
#define RTOT (NS*BBR)
#define QKVD 1536
#define HIDD 1024
#define GHID 128
#define SEH  64

// ---------------- scratch ----------------
// fp32 (stats only)
__device__ float  g_sesc[NS*FF];       // SE sigmoid scale
__device__ float  g_al  [NS*4];        // alpha
// fp16 (everything else)
__device__ __half g_Th  [RTOT*FF];     // tokens fp16 (residual base, LN input, pw GEMM A)
__device__ __half g_tA16[RTOT*FF];     // attention stream (fp16)
__device__ __half g_pw16[RTOT*FF];     // pw conv out -> depthwise out (in place)
__device__ __half g_x116[RTOT*FF];     // conv expert out (fp16)
__device__ __half g_h16 [RTOT*FF];     // LN-attn out / attn out / fuse out
__device__ __half g_h16b[RTOT*FF];     // LN-mlp out (computed early, used late)
__device__ __half g_qkv16[RTOT*QKVD];
__device__ __half g_hid16[RTOT*HIDD];
__device__ __half g_ctx16[NS*1024];
__device__ __half g_gh16 [NS*GHID];
__device__ __half g_se16 [NS*FF];      // SE squeeze (fp16)
__device__ __half g_seh16[NS*GHID];    // SE hidden, padded to 128
// fp16 weights, concatenated (element offsets); SE weights zero-padded
#define OFF_PW  0
#define OFF_IP  262144
#define OFF_AO  1048576
#define OFF_F1  1310720
#define OFF_F2  1835008
#define OFF_M1  2359296
#define OFF_M2  2883584
#define OFF_OP  3407872
#define OFF_G1  3670016
#define OFF_SE2 3801088            // 512 x 128 (K padded from 64)
#define OFF_SE1 3866624            // 128 x 512 (N padded from 64)
#define WTOT    3932160
__device__ __half g_w16[WTOT];

__device__ __forceinline__ float gelu_f(float x) {
    return 0.5f * x * (1.0f + erff(x * 0.70710678118654752440f));
}
__device__ __forceinline__ uint32_t h2u(float a, float b) {
    __half2 h = __floats2half2_rn(a, b);
    return *reinterpret_cast<uint32_t*>(&h);
}
__device__ __forceinline__ float2 u2f(uint32_t u) {
    __half2 h = *reinterpret_cast<__half2*>(&u);
    return make_float2(__low2float(h), __high2float(h));
}

__device__ __forceinline__ void mma_f16(float* c, const uint32_t* a, const uint32_t* b) {
    asm volatile(
        "mma.sync.aligned.m16n8k16.row.col.f32.f16.f16.f32 "
        "{%0,%1,%2,%3}, {%4,%5,%6,%7}, {%8,%9}, {%0,%1,%2,%3};"
        : "+f"(c[0]), "+f"(c[1]), "+f"(c[2]), "+f"(c[3])
        : "r"(a[0]), "r"(a[1]), "r"(a[2]), "r"(a[3]), "r"(b[0]), "r"(b[1]));
}
#define LDMX4(r0, r1, r2, r3, addr) \
    asm volatile("ldmatrix.sync.aligned.m8n8.x4.shared.b16 {%0,%1,%2,%3}, [%4];" \
                 : "=r"(r0), "=r"(r1), "=r"(r2), "=r"(r3) : "r"(addr))

#define CP16(dst, src) asm volatile("cp.async.cg.shared.global [%0], [%1], 16;" :: "r"(dst), "l"(src))
#define CP_COMMIT()    asm volatile("cp.async.commit_group;" ::: "memory")
#define CP_WAIT1()     asm volatile("cp.async.wait_group 1;" ::: "memory")
#define CP_WAIT0()     asm volatile("cp.async.wait_group 0;" ::: "memory")

// stage geometry: K-chunk 64 -> rows of 64 halves (128B) + 16B pad = 144B
// [3 stages][128 rows][144B] per operand
#define ROWB  144
#define STGB  18432u
#define WOFF  55296u              // 3 A stages
#define GEMM_SMEM 110592

// ---------------- main weights fp32 -> fp16, one launch ----------------
__global__ void cvt_all(const float* s0, const float* s1, const float* s2,
                        const float* s3, const float* s4, const float* s5,
                        const float* s6, const float* s7, const float* s8)
{
    int i = blockIdx.x * 256 + threadIdx.x;      // float4 index into g_w16
    if (i >= 950272) return;
    const float* s; int base;
    if      (i < 65536)  { s = s0; base = 0; }
    else if (i < 262144) { s = s1; base = 65536; }
    else if (i < 327680) { s = s2; base = 262144; }
    else if (i < 458752) { s = s3; base = 327680; }
    else if (i < 589824) { s = s4; base = 458752; }
    else if (i < 720896) { s = s5; base = 589824; }
    else if (i < 851968) { s = s6; base = 720896; }
    else if (i < 917504) { s = s7; base = 851968; }
    else                 { s = s8; base = 917504; }
    float4 v = ((const float4*)s)[i - base];
    uint2 o;
    o.x = h2u(v.x, v.y);
    o.y = h2u(v.z, v.w);
    ((uint2*)g_w16)[i] = o;
}

// ---------------- SE weights, zero-padded, fp32 -> fp16 ----------------
// se1p [128][512] (rows >= 64 zero), se2p [512][128] (cols >= 64 zero)
__global__ void cvt_se(const float* __restrict__ w1, const float* __restrict__ w2)
{
    int i = blockIdx.x * 256 + threadIdx.x;      // half2 index, 2*65536 total
    if (i < 65536) {
        const int r = i >> 8, c2 = i & 255;      // cols 2*c2, 2*c2+1
        uint32_t o = 0;
        if (r < 64) o = h2u(w1[r*512 + 2*c2], w1[r*512 + 2*c2 + 1]);
        ((uint32_t*)(g_w16 + OFF_SE1))[i] = o;
    } else {
        const int j = i - 65536;
        const int r = j >> 6, c2 = j & 63;
        uint32_t o = 0;
        if (c2 < 32) o = h2u(w2[r*64 + 2*c2], w2[r*64 + 2*c2 + 1]);
        ((uint32_t*)(g_w16 + OFF_SE2))[j] = o;
    }
}

// ---------------- FP16 tensor-core GEMM (K-chunk 64, 3-stage cp.async + ldmatrix) --
// C = epi(A[M,K] @ W[N,K]^T + bias [,+Res]).  256 threads, 8 warps (2x4),
// warp tile 64x32 (4x4 of m16n8k16), block tile 128x128, K chunk 64. K%64==0.
// EPI: 0 none->f16, 1 gelu->f16, 2 +Res(f16)->f16, 3 scatter(n,o,b)->f32,
//      4 relu->f16, 5 sigmoid->f32, 6 expert-fuse->f16
template<int EPI>
__global__ __launch_bounds__(256)
void gemm_hf(const __half* __restrict__ A, const __half* __restrict__ W,
             const float* __restrict__ bias, const __half* __restrict__ Res,
             void* __restrict__ Cv, int M, int N, int K)
{
    extern __shared__ uint32_t sm_[];

    const int bm   = blockIdx.y * 128;
    const int bn   = blockIdx.x * 128;
    const int tid  = threadIdx.x;
    const int wid  = tid >> 5;
    const int lane = tid & 31;
    const int wm   = wid & 1;
    const int wn   = wid >> 1;
    const int grp  = lane >> 2;
    const int tq   = lane & 3;

    // loaders: 2 threads per row, each covers 32 halves (four 16B chunks)
    const int lrow = tid >> 1;
    const int lh   = (tid & 1) * 32;
    const __half* aSrc = A + (size_t)(bm + lrow) * K + lh;
    const __half* wSrc = W + (size_t)(bn + lrow) * K + lh;
    uint32_t sbase;
    asm("{ .reg .u64 t; cvta.to.shared.u64 t, %1; cvt.u32.u64 %0, t; }" : "=r"(sbase) : "l"(sm_));
    const uint32_t dstA = sbase + (uint32_t)(lrow * ROWB + lh * 2);
    const uint32_t dstW = dstA + WOFF;

    // ldmatrix per-thread base addresses (stage 0)
    const uint32_t lmA = sbase + (uint32_t)((wm * 64 + (lane & 15)) * ROWB + (lane >> 4) * 16);
    const uint32_t lmB = sbase + WOFF +
        (uint32_t)((wn * 32 + (lane >> 4) * 8 + (lane & 7)) * ROWB + ((lane >> 3) & 1) * 16);

    float acc[4][4][4];
#pragma unroll
    for (int i = 0; i < 4; i++)
#pragma unroll
        for (int j = 0; j < 4; j++)
#pragma unroll
            for (int q = 0; q < 4; q++) acc[i][j][q] = 0.f;

    const int steps = K >> 6;

    auto issue = [&](int s) {
        const uint32_t so = (uint32_t)(s % 3) * STGB;
        const __half* a = aSrc + s * 64;
        const __half* w = wSrc + s * 64;
        CP16(dstA + so,      a);      CP16(dstA + so + 16, a + 8);
        CP16(dstA + so + 32, a + 16); CP16(dstA + so + 48, a + 24);
        CP16(dstW + so,      w);      CP16(dstW + so + 16, w + 8);
        CP16(dstW + so + 32, w + 16); CP16(dstW + so + 48, w + 24);
        CP_COMMIT();
    };

    issue(0);
    if (steps > 1) issue(1);

    for (int i = 0; i < steps; i++) {
        if (i + 1 < steps) { CP_WAIT1(); } else { CP_WAIT0(); }
        __syncthreads();

        const uint32_t so = (uint32_t)(i % 3) * STGB;
#pragma unroll
        for (int sub = 0; sub < 4; sub++) {
            const uint32_t ko = so + (uint32_t)sub * 32;   // 16 halves per k16
            uint32_t af[4][4], bf[4][2];
#pragma unroll
            for (int mt = 0; mt < 4; mt++)
                LDMX4(af[mt][0], af[mt][1], af[mt][2], af[mt][3],
                      lmA + ko + (uint32_t)(mt * 16 * ROWB));
#pragma unroll
            for (int p = 0; p < 2; p++)
                LDMX4(bf[p*2][0], bf[p*2][1], bf[p*2+1][0], bf[p*2+1][1],
                      lmB + ko + (uint32_t)(p * 16 * ROWB));
#pragma unroll
            for (int mt = 0; mt < 4; mt++)
#pragma unroll
                for (int nt = 0; nt < 4; nt++)
                    mma_f16(acc[mt][nt], af[mt], bf[nt]);
        }

        if (i + 2 < steps) issue(i + 2);   // slot (i+2)%3 == (i-1)%3: dead post-barrier
    }

    // ---------------- epilogue ----------------
#pragma unroll
    for (int mt = 0; mt < 4; mt++) {
        const int rbase = bm + wm * 64 + mt * 16 + grp;
#pragma unroll
        for (int nt = 0; nt < 4; nt++) {
            const int col = bn + wn * 32 + nt * 8 + tq * 2;
#pragma unroll
            for (int half = 0; half < 2; half++) {
                const int row = rbase + half * 8;
                float x = acc[mt][nt][half * 2 + 0];
                float y = acc[mt][nt][half * 2 + 1];
                if (bias) { x += bias[col]; y += bias[col + 1]; }
                if (EPI == 0) {
                    *(uint32_t*)&((__half*)Cv)[(size_t)row * N + col] = h2u(x, y);
                } else if (EPI == 1) {
                    *(uint32_t*)&((__half*)Cv)[(size_t)row * N + col] = h2u(gelu_f(x), gelu_f(y));
                } else if (EPI == 2) {
                    const size_t off = (size_t)row * N + col;
                    float2 rv = u2f(*(const uint32_t*)&Res[off]);
                    *(uint32_t*)&((__half*)Cv)[off] = h2u(x + rv.x, y + rv.y);
                } else if (EPI == 3) {
                    float* base = (float*)Cv + (size_t)(row >> 2) * 2048 + (row & 3);
                    base[col * 4]       = x;
                    base[(col + 1) * 4] = y;
                } else if (EPI == 4) {
                    *(uint32_t*)&((__half*)Cv)[(size_t)row * N + col] =
                        h2u(fmaxf(x, 0.f), fmaxf(y, 0.f));
                } else if (EPI == 5) {
                    *(float2*)&((float*)Cv)[(size_t)row * N + col] =
                        make_float2(1.f / (1.f + expf(-x)), 1.f / (1.f + expf(-y)));
                } else if (EPI == 6) {
                    // t3 = acc + bias + T(f16);  out = a0*x1 + a1*tA + a2*t3  (fp16)
                    const size_t off = (size_t)row * N + col;
                    float2 rv = u2f(*(const uint32_t*)&Res[off]);
                    x += rv.x; y += rv.y;
                    const int n = row >> 2;
                    const float a0 = g_al[n*4+0], a1 = g_al[n*4+1], a2 = g_al[n*4+2];
                    float2 u = u2f(*(const uint32_t*)&g_x116[off]);
                    float2 v = u2f(*(const uint32_t*)&g_tA16[off]);
                    float fx = a0*u.x + a1*v.x + a2*x;
                    float fy = a0*u.y + a1*v.y + a2*y;
                    *(uint32_t*)&((__half*)Cv)[off] = h2u(fx, fy);
                }
            }
        }
    }
}

// ---------------- transpose: fp16 tokens + fp16 gating ctx ----------------
__global__ void transpose_ctx_k(const float* __restrict__ br)
{
    const int n   = blockIdx.x;
    const int f0  = threadIdx.x * 4;   // 128 threads
    const float* src = br + (size_t)n * 2048;
    float4 r0 = *(const float4*)&src[(f0+0)*4];
    float4 r1 = *(const float4*)&src[(f0+1)*4];
    float4 r2 = *(const float4*)&src[(f0+2)*4];
    float4 r3 = *(const float4*)&src[(f0+3)*4];
    __half* th = g_Th + (size_t)n * 2048;
    *(uint2*)&th[0*512 + f0] = make_uint2(h2u(r0.x, r1.x), h2u(r2.x, r3.x));
    *(uint2*)&th[1*512 + f0] = make_uint2(h2u(r0.y, r1.y), h2u(r2.y, r3.y));
    *(uint2*)&th[2*512 + f0] = make_uint2(h2u(r0.z, r1.z), h2u(r2.z, r3.z));
    *(uint2*)&th[3*512 + f0] = make_uint2(h2u(r0.w, r1.w), h2u(r2.w, r3.w));
    __half* cx = g_ctx16 + (size_t)n * 1024;
    float m0 = 0.25f*(r0.x+r0.y+r0.z+r0.w), m1 = 0.25f*(r1.x+r1.y+r1.z+r1.w);
    float m2 = 0.25f*(r2.x+r2.y+r2.z+r2.w), m3 = 0.25f*(r3.x+r3.y+r3.z+r3.w);
    float x0 = fmaxf(fmaxf(r0.x,r0.y),fmaxf(r0.z,r0.w));
    float x1 = fmaxf(fmaxf(r1.x,r1.y),fmaxf(r1.z,r1.w));
    float x2 = fmaxf(fmaxf(r2.x,r2.y),fmaxf(r2.z,r2.w));
    float x3 = fmaxf(fmaxf(r3.x,r3.y),fmaxf(r3.z,r3.w));
    *(uint2*)&cx[f0]       = make_uint2(h2u(m0, m1), h2u(m2, m3));
    *(uint2*)&cx[512 + f0] = make_uint2(h2u(x0, x1), h2u(x2, x3));
}

// ---------------- LayerNorm (warp per row): fp16 in, fp16 out ----------------
__global__ void ln_k(const __half* __restrict__ X, const float* __restrict__ w,
                     const float* __restrict__ b, __half* __restrict__ Y, int rows)
{
    const int gw   = (int)((blockIdx.x * (size_t)blockDim.x + threadIdx.x) >> 5);
    const int lane = threadIdx.x & 31;
    if (gw >= rows) return;
    const __half* x = X + (size_t)gw * FF;
    float v[16];
    float s = 0.f, sq = 0.f;
#pragma unroll
    for (int i = 0; i < 4; i++) {
        uint2 u = *(const uint2*)&x[lane*4 + i*128];
        float2 ab = u2f(u.x), cd = u2f(u.y);
        v[i*4+0] = ab.x; v[i*4+1] = ab.y; v[i*4+2] = cd.x; v[i*4+3] = cd.y;
        s  += ab.x + ab.y + cd.x + cd.y;
        sq += ab.x*ab.x + ab.y*ab.y + cd.x*cd.x + cd.y*cd.y;
    }
#pragma unroll
    for (int o = 16; o > 0; o >>= 1) {
        s  += __shfl_xor_sync(~0u, s,  o);
        sq += __shfl_xor_sync(~0u, sq, o);
    }
    const float m   = s  * (1.f/FF);
    const float var = sq * (1.f/FF) - m*m;
    const float rs  = rsqrtf(var + 1e-5f);
    __half* y = Y + (size_t)gw * FF;
#pragma unroll
    for (int i = 0; i < 4; i++) {
        const int f = lane*4 + i*128;
        float4 wv = *(const float4*)&w[f];
        float4 bv = *(const float4*)&b[f];
        float o0 = (v[i*4+0] - m)*rs*wv.x + bv.x;
        float o1 = (v[i*4+1] - m)*rs*wv.y + bv.y;
        float o2 = (v[i*4+2] - m)*rs*wv.z + bv.z;
        float o3 = (v[i*4+3] - m)*rs*wv.w + bv.w;
        *(uint2*)&y[f] = make_uint2(h2u(o0, o1), h2u(o2, o3));
    }
}

// ---------------- dual LayerNorm over g_Th: one stats pass, two outputs ----------
__global__ void ln2_k(const __half* __restrict__ X,
                      const float* __restrict__ w1, const float* __restrict__ b1,
                      __half* __restrict__ Y1,
                      const float* __restrict__ w2, const float* __restrict__ b2,
                      __half* __restrict__ Y2, int rows)
{
    const int gw   = (int)((blockIdx.x * (size_t)blockDim.x + threadIdx.x) >> 5);
    const int lane = threadIdx.x & 31;
    if (gw >= rows) return;
    const __half* x = X + (size_t)gw * FF;
    float v[16];
    float s = 0.f, sq = 0.f;
#pragma unroll
    for (int i = 0; i < 4; i++) {
        uint2 u = *(const uint2*)&x[lane*4 + i*128];
        float2 ab = u2f(u.x), cd = u2f(u.y);
        v[i*4+0] = ab.x; v[i*4+1] = ab.y; v[i*4+2] = cd.x; v[i*4+3] = cd.y;
        s  += ab.x + ab.y + cd.x + cd.y;
        sq += ab.x*ab.x + ab.y*ab.y + cd.x*cd.x + cd.y*cd.y;
    }
#pragma unroll
    for (int o = 16; o > 0; o >>= 1) {
        s  += __shfl_xor_sync(~0u, s,  o);
        sq += __shfl_xor_sync(~0u, sq, o);
    }
    const float m   = s  * (1.f/FF);
    const float var = sq * (1.f/FF) - m*m;
    const float rs  = rsqrtf(var + 1e-5f);
    __half* y1 = Y1 + (size_t)gw * FF;
    __half* y2 = Y2 + (size_t)gw * FF;
#pragma unroll
    for (int i = 0; i < 4; i++) {
        const int f = lane*4 + i*128;
        const float nx = (v[i*4+0] - m)*rs, ny = (v[i*4+1] - m)*rs;
        const float nz = (v[i*4+2] - m)*rs, nw = (v[i*4+3] - m)*rs;
        float4 wa = *(const float4*)&w1[f];
        float4 ba = *(const float4*)&b1[f];
        *(uint2*)&y1[f] = make_uint2(h2u(nx*wa.x + ba.x, ny*wa.y + ba.y),
                                     h2u(nz*wa.z + ba.z, nw*wa.w + ba.w));
        float4 wb = *(const float4*)&w2[f];
        float4 bb = *(const float4*)&b2[f];
        *(uint2*)&y2[f] = make_uint2(h2u(nx*wb.x + bb.x, ny*wb.y + bb.y),
                                     h2u(nz*wb.z + bb.z, nw*wb.w + bb.w));
    }
}

// ---------------- depthwise conv IN PLACE on g_pw16 + SE squeeze (fp16) ----------
__global__ void dw_se_k(const float* __restrict__ dw)
{
    const int n  = blockIdx.x;
    const int f0 = threadIdx.x * 4;
    __half* p = g_pw16 + (size_t)n * 2048;
    float xb[4][4];
#pragma unroll
    for (int b = 0; b < 4; b++) {
        uint2 u = *(const uint2*)&p[b*512 + f0];
        float2 ab = u2f(u.x), cd = u2f(u.y);
        xb[b][0] = ab.x; xb[b][1] = ab.y; xb[b][2] = cd.x; xb[b][3] = cd.y;
    }
    float w0[4], w1[4], w2[4];
#pragma unroll
    for (int j = 0; j < 4; j++) {
        w0[j] = dw[(f0+j)*3 + 0];
        w1[j] = dw[(f0+j)*3 + 1];
        w2[j] = dw[(f0+j)*3 + 2];
    }
    float yb[4][4], sm[4];
#pragma unroll
    for (int j = 0; j < 4; j++) {
        yb[0][j] =                    w1[j]*xb[0][j] + w2[j]*xb[1][j];
        yb[1][j] = w0[j]*xb[0][j] + w1[j]*xb[1][j] + w2[j]*xb[2][j];
        yb[2][j] = w0[j]*xb[1][j] + w1[j]*xb[2][j] + w2[j]*xb[3][j];
        yb[3][j] = w0[j]*xb[2][j] + w1[j]*xb[3][j];
        sm[j] = 0.25f*(yb[0][j] + yb[1][j] + yb[2][j] + yb[3][j]);
    }
#pragma unroll
    for (int b = 0; b < 4; b++)
        *(uint2*)&p[b*512 + f0] = make_uint2(h2u(yb[b][0], yb[b][1]), h2u(yb[b][2], yb[b][3]));
    *(uint2*)&g_se16[(size_t)n*512 + f0] = make_uint2(h2u(sm[0], sm[1]), h2u(sm[2], sm[3]));
}

// ---------------- SE-scale + GroupNorm + GELU (fp16 in, fp16 out) ----------------
__global__ void gn_k(const float* __restrict__ SC,
                     const float* __restrict__ gw, const float* __restrict__ gb,
                     __half* __restrict__ Y)
{
    __shared__ float ws[8], wq[8], stats[2];
    const int n = blockIdx.x, tid = threadIdx.x;   // 256 threads, 4 half2 each
    const __half* x = g_pw16 + (size_t)n * 2048;
    const float* sc = SC + (size_t)n * 512;
    float v[8];
    float s = 0.f, sq = 0.f;
#pragma unroll
    for (int i = 0; i < 4; i++) {
        const int e2 = tid + i*256;          // half2 index, element e = e2*2
        const int e  = e2 * 2;
        float2 h = u2f(*(const uint32_t*)&x[e]);
        const int f = e & 511;
        float a = h.x * sc[f];
        float b = h.y * sc[f + 1];
        v[i*2]   = a; v[i*2+1] = b;
        s += a + b; sq += a*a + b*b;
    }
#pragma unroll
    for (int o = 16; o > 0; o >>= 1) {
        s  += __shfl_xor_sync(~0u, s,  o);
        sq += __shfl_xor_sync(~0u, sq, o);
    }
    if ((tid & 31) == 0) { ws[tid >> 5] = s; wq[tid >> 5] = sq; }
    __syncthreads();
    if (tid == 0) {
        float S = 0.f, Q = 0.f;
#pragma unroll
        for (int i = 0; i < 8; i++) { S += ws[i]; Q += wq[i]; }
        const float m = S * (1.f/2048.f);
        stats[0] = m;
        stats[1] = rsqrtf(Q * (1.f/2048.f) - m*m + 1e-5f);
    }
    __syncthreads();
    const float m = stats[0], r = stats[1];
    __half* y = Y + (size_t)n * 2048;
#pragma unroll
    for (int i = 0; i < 4; i++) {
        const int e2 = tid + i*256;
        const int e  = e2 * 2;
        const int f  = e & 511;
        float a = gelu_f((v[i*2]   - m) * r * gw[f]     + gb[f]);
        float b = gelu_f((v[i*2+1] - m) * r * gw[f + 1] + gb[f + 1]);
        *(uint32_t*)&y[e] = h2u(a, b);
    }
}

// ---------------- attention core (fp16 in/out, fp32 math) ----------------
__global__ void attn_k(const __half* __restrict__ QKV, __half* __restrict__ AO)
{
    const int n     = blockIdx.x;
    const int wid   = threadIdx.x >> 5;
    const int lane  = threadIdx.x & 31;
    const int dbase = wid*128 + lane*4;
    const __half* base = QKV + (size_t)n * 4 * 1536;
    float q[4][4], k[4][4], vv[4][4];
    const float sc = 0.08838834764831845f;
#pragma unroll
    for (int i = 0; i < 4; i++) {
        uint2 uq = *(const uint2*)&base[i*1536 +        dbase];
        uint2 uk = *(const uint2*)&base[i*1536 +  512 + dbase];
        uint2 uv = *(const uint2*)&base[i*1536 + 1024 + dbase];
        float2 q0 = u2f(uq.x), q1 = u2f(uq.y);
        float2 k0 = u2f(uk.x), k1 = u2f(uk.y);
        float2 v0 = u2f(uv.x), v1 = u2f(uv.y);
        q[i][0] = q0.x*sc; q[i][1] = q0.y*sc; q[i][2] = q1.x*sc; q[i][3] = q1.y*sc;
        k[i][0] = k0.x; k[i][1] = k0.y; k[i][2] = k1.x; k[i][3] = k1.y;
        vv[i][0] = v0.x; vv[i][1] = v0.y; vv[i][2] = v1.x; vv[i][3] = v1.y;
    }
    float p[4][4];
#pragma unroll
    for (int i = 0; i < 4; i++)
#pragma unroll
        for (int j = 0; j < 4; j++) {
            float d = q[i][0]*k[j][0] + q[i][1]*k[j][1] + q[i][2]*k[j][2] + q[i][3]*k[j][3];
#pragma unroll
            for (int o = 16; o > 0; o >>= 1) d += __shfl_xor_sync(~0u, d, o);
            p[i][j] = d;
        }
    __half* ao = AO + (size_t)n * 4 * 512;
#pragma unroll
    for (int i = 0; i < 4; i++) {
        const float m  = fmaxf(fmaxf(p[i][0], p[i][1]), fmaxf(p[i][2], p[i][3]));
        const float e0 = expf(p[i][0]-m), e1 = expf(p[i][1]-m);
        const float e2 = expf(p[i][2]-m), e3 = expf(p[i][3]-m);
        const float inv = 1.f / (e0+e1+e2+e3);
        float o0 = (e0*vv[0][0] + e1*vv[1][0] + e2*vv[2][0] + e3*vv[3][0]) * inv;
        float o1 = (e0*vv[0][1] + e1*vv[1][1] + e2*vv[2][1] + e3*vv[3][1]) * inv;
        float o2 = (e0*vv[0][2] + e1*vv[1][2] + e2*vv[2][2] + e3*vv[3][2]) * inv;
        float o3 = (e0*vv[0][3] + e1*vv[1][3] + e2*vv[2][3] + e3*vv[3][3]) * inv;
        *(uint2*)&ao[i*512 + dbase] = make_uint2(h2u(o0, o1), h2u(o2, o3));
    }
}

// ---------------- gate logits + softmax (fp16 hidden) ----------------
__global__ void gate2_k(const float* __restrict__ w2, const float* __restrict__ b2)
{
    const int n    = (int)((blockIdx.x * (size_t)blockDim.x + threadIdx.x) >> 5);
    const int lane = threadIdx.x & 31;
    if (n >= NS) return;
    const __half* h = g_gh16 + (size_t)n * 128;
    float lg[3];
#pragma unroll
    for (int e = 0; e < 3; e++) {
        float ps = __half2float(h[lane])      * w2[e*128 + lane]
                 + __half2float(h[lane + 32]) * w2[e*128 + lane + 32]
                 + __half2float(h[lane + 64]) * w2[e*128 + lane + 64]
                 + __half2float(h[lane + 96]) * w2[e*128 + lane + 96];
#pragma unroll
        for (int o = 16; o > 0; o >>= 1) ps += __shfl_xor_sync(~0u, ps, o);
        lg[e] = ps + b2[e];
    }
    if (lane == 0) {
        const float m  = fmaxf(lg[0], fmaxf(lg[1], lg[2]));
        const float e0 = expf(lg[0]-m), e1 = expf(lg[1]-m), e2 = expf(lg[2]-m);
        const float inv = 1.f / (e0+e1+e2);
        g_al[n*4+0] = e0*inv; g_al[n*4+1] = e1*inv; g_al[n*4+2] = e2*inv;
    }
}

// ---------------- launch ----------------
extern "C" void kernel_launch(void* const* d_in, const int* in_sizes, int n_in,
                              void* d_out, int out_size)
{
    (void)in_sizes; (void)n_in; (void)out_size;
    const float* br   = (const float*)d_in[0];
    const float* pw   = (const float*)d_in[1];
    const float* dww  = (const float*)d_in[2];
    const float* gnw  = (const float*)d_in[3];
    const float* gnb  = (const float*)d_in[4];
    const float* sew1 = (const float*)d_in[5];
    const float* sew2 = (const float*)d_in[6];
    const float* lnaw = (const float*)d_in[7];
    const float* lnab = (const float*)d_in[8];
    const float* ipw  = (const float*)d_in[9];
    const float* ipb  = (const float*)d_in[10];
    const float* aow  = (const float*)d_in[11];
    const float* aob  = (const float*)d_in[12];
    const float* lnfw = (const float*)d_in[13];
    const float* lnfb = (const float*)d_in[14];
    const float* f1w  = (const float*)d_in[15];
    const float* f1b  = (const float*)d_in[16];
    const float* f2w  = (const float*)d_in[17];
    const float* f2b  = (const float*)d_in[18];
    const float* mlw  = (const float*)d_in[19];
    const float* mlb  = (const float*)d_in[20];
    const float* m1w  = (const float*)d_in[21];
    const float* m1b  = (const float*)d_in[22];
    const float* m2w  = (const float*)d_in[23];
    const float* m2b  = (const float*)d_in[24];
    const float* g1w  = (const float*)d_in[25];
    const float* g1b  = (const float*)d_in[26];
    const float* g2w  = (const float*)d_in[27];
    const float* g2b  = (const float*)d_in[28];
    const float* opw  = (const float*)d_in[29];
    float* out = (float*)d_out;

    float  *pSESC;
    __half *pTh, *pTA16, *pPW16, *pX116, *pH16, *pH16b, *pQKV16, *pHID16, *pCTX16,
           *pGH16, *pSE16, *pSEH16, *pW16;
    cudaGetSymbolAddress((void**)&pSESC,  g_sesc);
    cudaGetSymbolAddress((void**)&pTh,    g_Th);
    cudaGetSymbolAddress((void**)&pTA16,  g_tA16);
    cudaGetSymbolAddress((void**)&pPW16,  g_pw16);
    cudaGetSymbolAddress((void**)&pX116,  g_x116);
    cudaGetSymbolAddress((void**)&pH16,   g_h16);
    cudaGetSymbolAddress((void**)&pH16b,  g_h16b);
    cudaGetSymbolAddress((void**)&pQKV16, g_qkv16);
    cudaGetSymbolAddress((void**)&pHID16, g_hid16);
    cudaGetSymbolAddress((void**)&pCTX16, g_ctx16);
    cudaGetSymbolAddress((void**)&pGH16,  g_gh16);
    cudaGetSymbolAddress((void**)&pSE16,  g_se16);
    cudaGetSymbolAddress((void**)&pSEH16, g_seh16);
    cudaGetSymbolAddress((void**)&pW16,   g_w16);

    cudaFuncSetAttribute(gemm_hf<0>, cudaFuncAttributeMaxDynamicSharedMemorySize, GEMM_SMEM);
    cudaFuncSetAttribute(gemm_hf<1>, cudaFuncAttributeMaxDynamicSharedMemorySize, GEMM_SMEM);
    cudaFuncSetAttribute(gemm_hf<2>, cudaFuncAttributeMaxDynamicSharedMemorySize, GEMM_SMEM);
    cudaFuncSetAttribute(gemm_hf<3>, cudaFuncAttributeMaxDynamicSharedMemorySize, GEMM_SMEM);
    cudaFuncSetAttribute(gemm_hf<4>, cudaFuncAttributeMaxDynamicSharedMemorySize, GEMM_SMEM);
    cudaFuncSetAttribute(gemm_hf<5>, cudaFuncAttributeMaxDynamicSharedMemorySize, GEMM_SMEM);
    cudaFuncSetAttribute(gemm_hf<6>, cudaFuncAttributeMaxDynamicSharedMemorySize, GEMM_SMEM);

    // 0. weights -> fp16 (main + zero-padded SE)
    cvt_all<<<3712, 256>>>(pw, ipw, aow, f1w, f2w, m1w, m2w, opw, g1w);
    cvt_se<<<512, 256>>>(sew1, sew2);

    // 1. tokens + gating context
    transpose_ctx_k<<<NS, 128>>>(br);
    // 2. gating MLP + softmax
    gemm_hf<1><<<dim3(1,128),256,GEMM_SMEM>>>(pCTX16, pW16+OFF_G1, g1b, nullptr, pGH16, NS, 128, 1024);
    gate2_k<<<NS/8, 256>>>(g2w, g2b);
    // 3. conv expert: pointwise conv
    gemm_hf<0><<<dim3(4,512),256,GEMM_SMEM>>>(pTh, pW16+OFF_PW, nullptr, nullptr, pPW16, RTOT, 512, 512);
    // 4. depthwise (in place) + SE squeeze
    dw_se_k<<<NS, 128>>>(dww);
    // 5. SE MLP (tensor cores, zero-padded)
    gemm_hf<4><<<dim3(1,128),256,GEMM_SMEM>>>(pSE16, pW16+OFF_SE1, nullptr, nullptr, pSEH16, NS, 128, 512);
    gemm_hf<5><<<dim3(4,128),256,GEMM_SMEM>>>(pSEH16, pW16+OFF_SE2, nullptr, nullptr, pSESC, NS, 512, 128);
    // 6. SE scale + GroupNorm + GELU -> x1 (fp16)
    gn_k<<<NS, 256>>>(pSESC, gnw, gnb, pX116);
    // 7. both LNs over Th in one pass (attn -> h16, mlp -> h16b)
    ln2_k<<<RTOT/8, 256>>>(pTh, lnaw, lnab, pH16, mlw, mlb, pH16b, RTOT);
    // 8. attention expert
    gemm_hf<0><<<dim3(12,512),256,GEMM_SMEM>>>(pH16, pW16+OFF_IP, ipb, nullptr, pQKV16, RTOT, 1536, 512);
    attn_k<<<NS, 128>>>(pQKV16, pH16);
    gemm_hf<2><<<dim3(4,512),256,GEMM_SMEM>>>(pH16, pW16+OFF_AO, aob, pTh, pTA16, RTOT, 512, 512);
    ln_k<<<RTOT/8, 256>>>(pTA16, lnfw, lnfb, pH16, RTOT);
    gemm_hf<1><<<dim3(8,512),256,GEMM_SMEM>>>(pH16, pW16+OFF_F1, f1b, nullptr, pHID16, RTOT, 1024, 512);
    gemm_hf<2><<<dim3(4,512),256,GEMM_SMEM>>>(pHID16, pW16+OFF_F2, f2b, pTA16, pTA16, RTOT, 512, 1024);
    // 9. mlp expert (m2 epilogue also does the 3-expert alpha fusion -> h16)
    gemm_hf<1><<<dim3(8,512),256,GEMM_SMEM>>>(pH16b, pW16+OFF_M1, m1b, nullptr, pHID16, RTOT, 1024, 512);
    gemm_hf<6><<<dim3(4,512),256,GEMM_SMEM>>>(pHID16, pW16+OFF_M2, m2b, pTh, pH16, RTOT, 512, 1024);
    // 10. output projection (scatter to (n,o,b))
    gemm_hf<3><<<dim3(4,512),256,GEMM_SMEM>>>(pH16, pW16+OFF_OP, nullptr, nullptr, out, RTOT, 512, 512);
}

// round 15
// speedup vs baseline: 1.0012x; 1.0012x over previous
#include <cuda_runtime.h>
#include <cuda_fp16.h>
#include <math.h>
#include <stdint.h>

// ---------------- problem constants ----------------
#define NS   16384
#define FF   512
#define BBR  4
#define RTOT (NS*BBR)
#define QKVD 1536
#define HIDD 1024
#define GHID 128
#define SEH  64

// ---------------- scratch ----------------
// fp32 (stats only)
__device__ float  g_sesc[NS*FF];       // SE sigmoid scale
__device__ float  g_al  [NS*4];        // alpha
// fp16 (everything else)
__device__ __half g_Th  [RTOT*FF];     // tokens fp16 (residual base, LN input, pw GEMM A)
__device__ __half g_tA16[RTOT*FF];     // attention stream (fp16)
__device__ __half g_pw16[RTOT*FF];     // pw conv out -> depthwise out (in place)
__device__ __half g_x116[RTOT*FF];     // conv expert out (fp16)
__device__ __half g_h16 [RTOT*FF];     // LN-attn out / attn out / fuse out
__device__ __half g_h16b[RTOT*FF];     // LN-mlp out (computed early, used late)
__device__ __half g_qkv16[RTOT*QKVD];
__device__ __half g_hid16[RTOT*HIDD];
__device__ __half g_ctx16[NS*1024];
__device__ __half g_gh16 [NS*GHID];
__device__ __half g_se16 [NS*FF];      // SE squeeze (fp16)
__device__ __half g_seh16[NS*GHID];    // SE hidden, padded to 128
// fp16 weights, concatenated (element offsets); SE weights zero-padded
#define OFF_PW  0
#define OFF_IP  262144
#define OFF_AO  1048576
#define OFF_F1  1310720
#define OFF_F2  1835008
#define OFF_M1  2359296
#define OFF_M2  2883584
#define OFF_OP  3407872
#define OFF_G1  3670016
#define OFF_SE2 3801088            // 512 x 128 (K padded from 64)
#define OFF_SE1 3866624            // 128 x 512 (N padded from 64)
#define WTOT    3932160
__device__ __half g_w16[WTOT];

__device__ __forceinline__ float gelu_f(float x) {
    return 0.5f * x * (1.0f + erff(x * 0.70710678118654752440f));
}
__device__ __forceinline__ uint32_t h2u(float a, float b) {
    __half2 h = __floats2half2_rn(a, b);
    return *reinterpret_cast<uint32_t*>(&h);
}
__device__ __forceinline__ float2 u2f(uint32_t u) {
    __half2 h = *reinterpret_cast<__half2*>(&u);
    return make_float2(__low2float(h), __high2float(h));
}

__device__ __forceinline__ void mma_f16(float* c, const uint32_t* a, const uint32_t* b) {
    asm volatile(
        "mma.sync.aligned.m16n8k16.row.col.f32.f16.f16.f32 "
        "{%0,%1,%2,%3}, {%4,%5,%6,%7}, {%8,%9}, {%0,%1,%2,%3};"
        : "+f"(c[0]), "+f"(c[1]), "+f"(c[2]), "+f"(c[3])
        : "r"(a[0]), "r"(a[1]), "r"(a[2]), "r"(a[3]), "r"(b[0]), "r"(b[1]));
}
#define LDMX4(r0, r1, r2, r3, addr) \
    asm volatile("ldmatrix.sync.aligned.m8n8.x4.shared.b16 {%0,%1,%2,%3}, [%4];" \
                 : "=r"(r0), "=r"(r1), "=r"(r2), "=r"(r3) : "r"(addr))

#define CP16(dst, src) asm volatile("cp.async.cg.shared.global [%0], [%1], 16;" :: "r"(dst), "l"(src))
#define CP_COMMIT()    asm volatile("cp.async.commit_group;" ::: "memory")
#define CP_WAIT1()     asm volatile("cp.async.wait_group 1;" ::: "memory")
#define CP_WAIT0()     asm volatile("cp.async.wait_group 0;" ::: "memory")

// stage geometry: K-chunk 64 -> rows of 64 halves (128B) + 16B pad = 144B
// [3 stages][128 rows][144B] per operand
#define ROWB  144
#define STGB  18432u
#define WOFF  55296u              // 3 A stages
#define GEMM_SMEM 110592

// ---------------- main weights fp32 -> fp16, one launch ----------------
__global__ void cvt_all(const float* s0, const float* s1, const float* s2,
                        const float* s3, const float* s4, const float* s5,
                        const float* s6, const float* s7, const float* s8)
{
    int i = blockIdx.x * 256 + threadIdx.x;      // float4 index into g_w16
    if (i >= 950272) return;
    const float* s; int base;
    if      (i < 65536)  { s = s0; base = 0; }
    else if (i < 262144) { s = s1; base = 65536; }
    else if (i < 327680) { s = s2; base = 262144; }
    else if (i < 458752) { s = s3; base = 327680; }
    else if (i < 589824) { s = s4; base = 458752; }
    else if (i < 720896) { s = s5; base = 589824; }
    else if (i < 851968) { s = s6; base = 720896; }
    else if (i < 917504) { s = s7; base = 851968; }
    else                 { s = s8; base = 917504; }
    float4 v = ((const float4*)s)[i - base];
    uint2 o;
    o.x = h2u(v.x, v.y);
    o.y = h2u(v.z, v.w);
    ((uint2*)g_w16)[i] = o;
}

// ---------------- SE weights, zero-padded, fp32 -> fp16 ----------------
// se1p [128][512] (rows >= 64 zero), se2p [512][128] (cols >= 64 zero)
__global__ void cvt_se(const float* __restrict__ w1, const float* __restrict__ w2)
{
    int i = blockIdx.x * 256 + threadIdx.x;      // half2 index, 2*65536 total
    if (i < 65536) {
        const int r = i >> 8, c2 = i & 255;      // cols 2*c2, 2*c2+1
        uint32_t o = 0;
        if (r < 64) o = h2u(w1[r*512 + 2*c2], w1[r*512 + 2*c2 + 1]);
        ((uint32_t*)(g_w16 + OFF_SE1))[i] = o;
    } else {
        const int j = i - 65536;
        const int r = j >> 6, c2 = j & 63;
        uint32_t o = 0;
        if (c2 < 32) o = h2u(w2[r*64 + 2*c2], w2[r*64 + 2*c2 + 1]);
        ((uint32_t*)(g_w16 + OFF_SE2))[j] = o;
    }
}

// ---------------- FP16 tensor-core GEMM (K-chunk 64, 3-stage cp.async + ldmatrix) --
// C = epi(A[M,K] @ W[N,K]^T + bias [,+Res]).  256 threads, 8 warps (2x4),
// warp tile 64x32 (4x4 of m16n8k16), block tile 128x128, K chunk 64. K%64==0.
// EPI: 0 none->f16, 1 gelu->f16, 2 +Res(f16)->f16, 3 scatter(n,o,b)->f32,
//      4 relu->f16, 5 sigmoid->f32, 6 expert-fuse->f16
template<int EPI>
__global__ __launch_bounds__(256)
void gemm_hf(const __half* __restrict__ A, const __half* __restrict__ W,
             const float* __restrict__ bias, const __half* __restrict__ Res,
             void* __restrict__ Cv, int M, int N, int K)
{
    extern __shared__ uint32_t sm_[];

    const int bm   = blockIdx.y * 128;
    const int bn   = blockIdx.x * 128;
    const int tid  = threadIdx.x;
    const int wid  = tid >> 5;
    const int lane = tid & 31;
    const int wm   = wid & 1;
    const int wn   = wid >> 1;
    const int grp  = lane >> 2;
    const int tq   = lane & 3;

    // loaders: 2 threads per row, each covers 32 halves (four 16B chunks)
    const int lrow = tid >> 1;
    const int lh   = (tid & 1) * 32;
    const __half* aSrc = A + (size_t)(bm + lrow) * K + lh;
    const __half* wSrc = W + (size_t)(bn + lrow) * K + lh;
    uint32_t sbase;
    asm("{ .reg .u64 t; cvta.to.shared.u64 t, %1; cvt.u32.u64 %0, t; }" : "=r"(sbase) : "l"(sm_));
    const uint32_t dstA = sbase + (uint32_t)(lrow * ROWB + lh * 2);
    const uint32_t dstW = dstA + WOFF;

    // ldmatrix per-thread base addresses (stage 0)
    const uint32_t lmA = sbase + (uint32_t)((wm * 64 + (lane & 15)) * ROWB + (lane >> 4) * 16);
    const uint32_t lmB = sbase + WOFF +
        (uint32_t)((wn * 32 + (lane >> 4) * 8 + (lane & 7)) * ROWB + ((lane >> 3) & 1) * 16);

    float acc[4][4][4];
#pragma unroll
    for (int i = 0; i < 4; i++)
#pragma unroll
        for (int j = 0; j < 4; j++)
#pragma unroll
            for (int q = 0; q < 4; q++) acc[i][j][q] = 0.f;

    const int steps = K >> 6;

    auto issue = [&](int s) {
        const uint32_t so = (uint32_t)(s % 3) * STGB;
        const __half* a = aSrc + s * 64;
        const __half* w = wSrc + s * 64;
        CP16(dstA + so,      a);      CP16(dstA + so + 16, a + 8);
        CP16(dstA + so + 32, a + 16); CP16(dstA + so + 48, a + 24);
        CP16(dstW + so,      w);      CP16(dstW + so + 16, w + 8);
        CP16(dstW + so + 32, w + 16); CP16(dstW + so + 48, w + 24);
        CP_COMMIT();
    };

    issue(0);
    if (steps > 1) issue(1);

    for (int i = 0; i < steps; i++) {
        if (i + 1 < steps) { CP_WAIT1(); } else { CP_WAIT0(); }
        __syncthreads();

        const uint32_t so = (uint32_t)(i % 3) * STGB;
#pragma unroll
        for (int sub = 0; sub < 4; sub++) {
            const uint32_t ko = so + (uint32_t)sub * 32;   // 16 halves per k16
            uint32_t af[4][4], bf[4][2];
#pragma unroll
            for (int mt = 0; mt < 4; mt++)
                LDMX4(af[mt][0], af[mt][1], af[mt][2], af[mt][3],
                      lmA + ko + (uint32_t)(mt * 16 * ROWB));
#pragma unroll
            for (int p = 0; p < 2; p++)
                LDMX4(bf[p*2][0], bf[p*2][1], bf[p*2+1][0], bf[p*2+1][1],
                      lmB + ko + (uint32_t)(p * 16 * ROWB));
#pragma unroll
            for (int mt = 0; mt < 4; mt++)
#pragma unroll
                for (int nt = 0; nt < 4; nt++)
                    mma_f16(acc[mt][nt], af[mt], bf[nt]);
        }

        if (i + 2 < steps) issue(i + 2);   // slot (i+2)%3 == (i-1)%3: dead post-barrier
    }

    // ---------------- epilogue ----------------
#pragma unroll
    for (int mt = 0; mt < 4; mt++) {
        const int rbase = bm + wm * 64 + mt * 16 + grp;
#pragma unroll
        for (int nt = 0; nt < 4; nt++) {
            const int col = bn + wn * 32 + nt * 8 + tq * 2;
#pragma unroll
            for (int half = 0; half < 2; half++) {
                const int row = rbase + half * 8;
                float x = acc[mt][nt][half * 2 + 0];
                float y = acc[mt][nt][half * 2 + 1];
                if (bias) { x += bias[col]; y += bias[col + 1]; }
                if (EPI == 0) {
                    *(uint32_t*)&((__half*)Cv)[(size_t)row * N + col] = h2u(x, y);
                } else if (EPI == 1) {
                    *(uint32_t*)&((__half*)Cv)[(size_t)row * N + col] = h2u(gelu_f(x), gelu_f(y));
                } else if (EPI == 2) {
                    const size_t off = (size_t)row * N + col;
                    float2 rv = u2f(*(const uint32_t*)&Res[off]);
                    *(uint32_t*)&((__half*)Cv)[off] = h2u(x + rv.x, y + rv.y);
                } else if (EPI == 3) {
                    float* base = (float*)Cv + (size_t)(row >> 2) * 2048 + (row & 3);
                    base[col * 4]       = x;
                    base[(col + 1) * 4] = y;
                } else if (EPI == 4) {
                    *(uint32_t*)&((__half*)Cv)[(size_t)row * N + col] =
                        h2u(fmaxf(x, 0.f), fmaxf(y, 0.f));
                } else if (EPI == 5) {
                    *(float2*)&((float*)Cv)[(size_t)row * N + col] =
                        make_float2(1.f / (1.f + expf(-x)), 1.f / (1.f + expf(-y)));
                } else if (EPI == 6) {
                    // t3 = acc + bias + T(f16);  out = a0*x1 + a1*tA + a2*t3  (fp16)
                    const size_t off = (size_t)row * N + col;
                    float2 rv = u2f(*(const uint32_t*)&Res[off]);
                    x += rv.x; y += rv.y;
                    const int n = row >> 2;
                    const float a0 = g_al[n*4+0], a1 = g_al[n*4+1], a2 = g_al[n*4+2];
                    float2 u = u2f(*(const uint32_t*)&g_x116[off]);
                    float2 v = u2f(*(const uint32_t*)&g_tA16[off]);
                    float fx = a0*u.x + a1*v.x + a2*x;
                    float fy = a0*u.y + a1*v.y + a2*y;
                    *(uint32_t*)&((__half*)Cv)[off] = h2u(fx, fy);
                }
            }
        }
    }
}

// ---------------- transpose: fp16 tokens + fp16 gating ctx ----------------
__global__ void transpose_ctx_k(const float* __restrict__ br)
{
    const int n   = blockIdx.x;
    const int f0  = threadIdx.x * 4;   // 128 threads
    const float* src = br + (size_t)n * 2048;
    float4 r0 = *(const float4*)&src[(f0+0)*4];
    float4 r1 = *(const float4*)&src[(f0+1)*4];
    float4 r2 = *(const float4*)&src[(f0+2)*4];
    float4 r3 = *(const float4*)&src[(f0+3)*4];
    __half* th = g_Th + (size_t)n * 2048;
    *(uint2*)&th[0*512 + f0] = make_uint2(h2u(r0.x, r1.x), h2u(r2.x, r3.x));
    *(uint2*)&th[1*512 + f0] = make_uint2(h2u(r0.y, r1.y), h2u(r2.y, r3.y));
    *(uint2*)&th[2*512 + f0] = make_uint2(h2u(r0.z, r1.z), h2u(r2.z, r3.z));
    *(uint2*)&th[3*512 + f0] = make_uint2(h2u(r0.w, r1.w), h2u(r2.w, r3.w));
    __half* cx = g_ctx16 + (size_t)n * 1024;
    float m0 = 0.25f*(r0.x+r0.y+r0.z+r0.w), m1 = 0.25f*(r1.x+r1.y+r1.z+r1.w);
    float m2 = 0.25f*(r2.x+r2.y+r2.z+r2.w), m3 = 0.25f*(r3.x+r3.y+r3.z+r3.w);
    float x0 = fmaxf(fmaxf(r0.x,r0.y),fmaxf(r0.z,r0.w));
    float x1 = fmaxf(fmaxf(r1.x,r1.y),fmaxf(r1.z,r1.w));
    float x2 = fmaxf(fmaxf(r2.x,r2.y),fmaxf(r2.z,r2.w));
    float x3 = fmaxf(fmaxf(r3.x,r3.y),fmaxf(r3.z,r3.w));
    *(uint2*)&cx[f0]       = make_uint2(h2u(m0, m1), h2u(m2, m3));
    *(uint2*)&cx[512 + f0] = make_uint2(h2u(x0, x1), h2u(x2, x3));
}

// ---------------- LayerNorm (warp per row): fp16 in, fp16 out ----------------
__global__ void ln_k(const __half* __restrict__ X, const float* __restrict__ w,
                     const float* __restrict__ b, __half* __restrict__ Y, int rows)
{
    const int gw   = (int)((blockIdx.x * (size_t)blockDim.x + threadIdx.x) >> 5);
    const int lane = threadIdx.x & 31;
    if (gw >= rows) return;
    const __half* x = X + (size_t)gw * FF;
    float v[16];
    float s = 0.f, sq = 0.f;
#pragma unroll
    for (int i = 0; i < 4; i++) {
        uint2 u = *(const uint2*)&x[lane*4 + i*128];
        float2 ab = u2f(u.x), cd = u2f(u.y);
        v[i*4+0] = ab.x; v[i*4+1] = ab.y; v[i*4+2] = cd.x; v[i*4+3] = cd.y;
        s  += ab.x + ab.y + cd.x + cd.y;
        sq += ab.x*ab.x + ab.y*ab.y + cd.x*cd.x + cd.y*cd.y;
    }
#pragma unroll
    for (int o = 16; o > 0; o >>= 1) {
        s  += __shfl_xor_sync(~0u, s,  o);
        sq += __shfl_xor_sync(~0u, sq, o);
    }
    const float m   = s  * (1.f/FF);
    const float var = sq * (1.f/FF) - m*m;
    const float rs  = rsqrtf(var + 1e-5f);
    __half* y = Y + (size_t)gw * FF;
#pragma unroll
    for (int i = 0; i < 4; i++) {
        const int f = lane*4 + i*128;
        float4 wv = *(const float4*)&w[f];
        float4 bv = *(const float4*)&b[f];
        float o0 = (v[i*4+0] - m)*rs*wv.x + bv.x;
        float o1 = (v[i*4+1] - m)*rs*wv.y + bv.y;
        float o2 = (v[i*4+2] - m)*rs*wv.z + bv.z;
        float o3 = (v[i*4+3] - m)*rs*wv.w + bv.w;
        *(uint2*)&y[f] = make_uint2(h2u(o0, o1), h2u(o2, o3));
    }
}

// ---------------- dual LayerNorm over g_Th: one stats pass, two outputs ----------
__global__ void ln2_k(const __half* __restrict__ X,
                      const float* __restrict__ w1, const float* __restrict__ b1,
                      __half* __restrict__ Y1,
                      const float* __restrict__ w2, const float* __restrict__ b2,
                      __half* __restrict__ Y2, int rows)
{
    const int gw   = (int)((blockIdx.x * (size_t)blockDim.x + threadIdx.x) >> 5);
    const int lane = threadIdx.x & 31;
    if (gw >= rows) return;
    const __half* x = X + (size_t)gw * FF;
    float v[16];
    float s = 0.f, sq = 0.f;
#pragma unroll
    for (int i = 0; i < 4; i++) {
        uint2 u = *(const uint2*)&x[lane*4 + i*128];
        float2 ab = u2f(u.x), cd = u2f(u.y);
        v[i*4+0] = ab.x; v[i*4+1] = ab.y; v[i*4+2] = cd.x; v[i*4+3] = cd.y;
        s  += ab.x + ab.y + cd.x + cd.y;
        sq += ab.x*ab.x + ab.y*ab.y + cd.x*cd.x + cd.y*cd.y;
    }
#pragma unroll
    for (int o = 16; o > 0; o >>= 1) {
        s  += __shfl_xor_sync(~0u, s,  o);
        sq += __shfl_xor_sync(~0u, sq, o);
    }
    const float m   = s  * (1.f/FF);
    const float var = sq * (1.f/FF) - m*m;
    const float rs  = rsqrtf(var + 1e-5f);
    __half* y1 = Y1 + (size_t)gw * FF;
    __half* y2 = Y2 + (size_t)gw * FF;
#pragma unroll
    for (int i = 0; i < 4; i++) {
        const int f = lane*4 + i*128;
        const float nx = (v[i*4+0] - m)*rs, ny = (v[i*4+1] - m)*rs;
        const float nz = (v[i*4+2] - m)*rs, nw = (v[i*4+3] - m)*rs;
        float4 wa = *(const float4*)&w1[f];
        float4 ba = *(const float4*)&b1[f];
        *(uint2*)&y1[f] = make_uint2(h2u(nx*wa.x + ba.x, ny*wa.y + ba.y),
                                     h2u(nz*wa.z + ba.z, nw*wa.w + ba.w));
        float4 wb = *(const float4*)&w2[f];
        float4 bb = *(const float4*)&b2[f];
        *(uint2*)&y2[f] = make_uint2(h2u(nx*wb.x + bb.x, ny*wb.y + bb.y),
                                     h2u(nz*wb.z + bb.z, nw*wb.w + bb.w));
    }
}

// ---------------- depthwise conv IN PLACE on g_pw16 + SE squeeze (fp16) ----------
__global__ void dw_se_k(const float* __restrict__ dw)
{
    const int n  = blockIdx.x;
    const int f0 = threadIdx.x * 4;
    __half* p = g_pw16 + (size_t)n * 2048;
    float xb[4][4];
#pragma unroll
    for (int b = 0; b < 4; b++) {
        uint2 u = *(const uint2*)&p[b*512 + f0];
        float2 ab = u2f(u.x), cd = u2f(u.y);
        xb[b][0] = ab.x; xb[b][1] = ab.y; xb[b][2] = cd.x; xb[b][3] = cd.y;
    }
    float w0[4], w1[4], w2[4];
#pragma unroll
    for (int j = 0; j < 4; j++) {
        w0[j] = dw[(f0+j)*3 + 0];
        w1[j] = dw[(f0+j)*3 + 1];
        w2[j] = dw[(f0+j)*3 + 2];
    }
    float yb[4][4], sm[4];
#pragma unroll
    for (int j = 0; j < 4; j++) {
        yb[0][j] =                    w1[j]*xb[0][j] + w2[j]*xb[1][j];
        yb[1][j] = w0[j]*xb[0][j] + w1[j]*xb[1][j] + w2[j]*xb[2][j];
        yb[2][j] = w0[j]*xb[1][j] + w1[j]*xb[2][j] + w2[j]*xb[3][j];
        yb[3][j] = w0[j]*xb[2][j] + w1[j]*xb[3][j];
        sm[j] = 0.25f*(yb[0][j] + yb[1][j] + yb[2][j] + yb[3][j]);
    }
#pragma unroll
    for (int b = 0; b < 4; b++)
        *(uint2*)&p[b*512 + f0] = make_uint2(h2u(yb[b][0], yb[b][1]), h2u(yb[b][2], yb[b][3]));
    *(uint2*)&g_se16[(size_t)n*512 + f0] = make_uint2(h2u(sm[0], sm[1]), h2u(sm[2], sm[3]));
}

// ---------------- SE-scale + GroupNorm + GELU (fp16 in, fp16 out) ----------------
__global__ void gn_k(const float* __restrict__ SC,
                     const float* __restrict__ gw, const float* __restrict__ gb,
                     __half* __restrict__ Y)
{
    __shared__ float ws[8], wq[8], stats[2];
    const int n = blockIdx.x, tid = threadIdx.x;   // 256 threads, 4 half2 each
    const __half* x = g_pw16 + (size_t)n * 2048;
    const float* sc = SC + (size_t)n * 512;
    float v[8];
    float s = 0.f, sq = 0.f;
#pragma unroll
    for (int i = 0; i < 4; i++) {
        const int e2 = tid + i*256;          // half2 index, element e = e2*2
        const int e  = e2 * 2;
        float2 h = u2f(*(const uint32_t*)&x[e]);
        const int f = e & 511;
        float a = h.x * sc[f];
        float b = h.y * sc[f + 1];
        v[i*2]   = a; v[i*2+1] = b;
        s += a + b; sq += a*a + b*b;
    }
#pragma unroll
    for (int o = 16; o > 0; o >>= 1) {
        s  += __shfl_xor_sync(~0u, s,  o);
        sq += __shfl_xor_sync(~0u, sq, o);
    }
    if ((tid & 31) == 0) { ws[tid >> 5] = s; wq[tid >> 5] = sq; }
    __syncthreads();
    if (tid == 0) {
        float S = 0.f, Q = 0.f;
#pragma unroll
        for (int i = 0; i < 8; i++) { S += ws[i]; Q += wq[i]; }
        const float m = S * (1.f/2048.f);
        stats[0] = m;
        stats[1] = rsqrtf(Q * (1.f/2048.f) - m*m + 1e-5f);
    }
    __syncthreads();
    const float m = stats[0], r = stats[1];
    __half* y = Y + (size_t)n * 2048;
#pragma unroll
    for (int i = 0; i < 4; i++) {
        const int e2 = tid + i*256;
        const int e  = e2 * 2;
        const int f  = e & 511;
        float a = gelu_f((v[i*2]   - m) * r * gw[f]     + gb[f]);
        float b = gelu_f((v[i*2+1] - m) * r * gw[f + 1] + gb[f + 1]);
        *(uint32_t*)&y[e] = h2u(a, b);
    }
}

// ---------------- attention core (fp16 in/out, fp32 math) ----------------
__global__ void attn_k(const __half* __restrict__ QKV, __half* __restrict__ AO)
{
    const int n     = blockIdx.x;
    const int wid   = threadIdx.x >> 5;
    const int lane  = threadIdx.x & 31;
    const int dbase = wid*128 + lane*4;
    const __half* base = QKV + (size_t)n * 4 * 1536;
    float q[4][4], k[4][4], vv[4][4];
    const float sc = 0.08838834764831845f;
#pragma unroll
    for (int i = 0; i < 4; i++) {
        uint2 uq = *(const uint2*)&base[i*1536 +        dbase];
        uint2 uk = *(const uint2*)&base[i*1536 +  512 + dbase];
        uint2 uv = *(const uint2*)&base[i*1536 + 1024 + dbase];
        float2 q0 = u2f(uq.x), q1 = u2f(uq.y);
        float2 k0 = u2f(uk.x), k1 = u2f(uk.y);
        float2 v0 = u2f(uv.x), v1 = u2f(uv.y);
        q[i][0] = q0.x*sc; q[i][1] = q0.y*sc; q[i][2] = q1.x*sc; q[i][3] = q1.y*sc;
        k[i][0] = k0.x; k[i][1] = k0.y; k[i][2] = k1.x; k[i][3] = k1.y;
        vv[i][0] = v0.x; vv[i][1] = v0.y; vv[i][2] = v1.x; vv[i][3] = v1.y;
    }
    float p[4][4];
#pragma unroll
    for (int i = 0; i < 4; i++)
#pragma unroll
        for (int j = 0; j < 4; j++) {
            float d = q[i][0]*k[j][0] + q[i][1]*k[j][1] + q[i][2]*k[j][2] + q[i][3]*k[j][3];
#pragma unroll
            for (int o = 16; o > 0; o >>= 1) d += __shfl_xor_sync(~0u, d, o);
            p[i][j] = d;
        }
    __half* ao = AO + (size_t)n * 4 * 512;
#pragma unroll
    for (int i = 0; i < 4; i++) {
        const float m  = fmaxf(fmaxf(p[i][0], p[i][1]), fmaxf(p[i][2], p[i][3]));
        const float e0 = expf(p[i][0]-m), e1 = expf(p[i][1]-m);
        const float e2 = expf(p[i][2]-m), e3 = expf(p[i][3]-m);
        const float inv = 1.f / (e0+e1+e2+e3);
        float o0 = (e0*vv[0][0] + e1*vv[1][0] + e2*vv[2][0] + e3*vv[3][0]) * inv;
        float o1 = (e0*vv[0][1] + e1*vv[1][1] + e2*vv[2][1] + e3*vv[3][1]) * inv;
        float o2 = (e0*vv[0][2] + e1*vv[1][2] + e2*vv[2][2] + e3*vv[3][2]) * inv;
        float o3 = (e0*vv[0][3] + e1*vv[1][3] + e2*vv[2][3] + e3*vv[3][3]) * inv;
        *(uint2*)&ao[i*512 + dbase] = make_uint2(h2u(o0, o1), h2u(o2, o3));
    }
}

// ---------------- gate logits + softmax (fp16 hidden) ----------------
__global__ void gate2_k(const float* __restrict__ w2, const float* __restrict__ b2)
{
    const int n    = (int)((blockIdx.x * (size_t)blockDim.x + threadIdx.x) >> 5);
    const int lane = threadIdx.x & 31;
    if (n >= NS) return;
    const __half* h = g_gh16 + (size_t)n * 128;
    float lg[3];
#pragma unroll
    for (int e = 0; e < 3; e++) {
        float ps = __half2float(h[lane])      * w2[e*128 + lane]
                 + __half2float(h[lane + 32]) * w2[e*128 + lane + 32]
                 + __half2float(h[lane + 64]) * w2[e*128 + lane + 64]
                 + __half2float(h[lane + 96]) * w2[e*128 + lane + 96];
#pragma unroll
        for (int o = 16; o > 0; o >>= 1) ps += __shfl_xor_sync(~0u, ps, o);
        lg[e] = ps + b2[e];
    }
    if (lane == 0) {
        const float m  = fmaxf(lg[0], fmaxf(lg[1], lg[2]));
        const float e0 = expf(lg[0]-m), e1 = expf(lg[1]-m), e2 = expf(lg[2]-m);
        const float inv = 1.f / (e0+e1+e2);
        g_al[n*4+0] = e0*inv; g_al[n*4+1] = e1*inv; g_al[n*4+2] = e2*inv;
    }
}

// ---------------- launch ----------------
extern "C" void kernel_launch(void* const* d_in, const int* in_sizes, int n_in,
                              void* d_out, int out_size)
{
    (void)in_sizes; (void)n_in; (void)out_size;
    const float* br   = (const float*)d_in[0];
    const float* pw   = (const float*)d_in[1];
    const float* dww  = (const float*)d_in[2];
    const float* gnw  = (const float*)d_in[3];
    const float* gnb  = (const float*)d_in[4];
    const float* sew1 = (const float*)d_in[5];
    const float* sew2 = (const float*)d_in[6];
    const float* lnaw = (const float*)d_in[7];
    const float* lnab = (const float*)d_in[8];
    const float* ipw  = (const float*)d_in[9];
    const float* ipb  = (const float*)d_in[10];
    const float* aow  = (const float*)d_in[11];
    const float* aob  = (const float*)d_in[12];
    const float* lnfw = (const float*)d_in[13];
    const float* lnfb = (const float*)d_in[14];
    const float* f1w  = (const float*)d_in[15];
    const float* f1b  = (const float*)d_in[16];
    const float* f2w  = (const float*)d_in[17];
    const float* f2b  = (const float*)d_in[18];
    const float* mlw  = (const float*)d_in[19];
    const float* mlb  = (const float*)d_in[20];
    const float* m1w  = (const float*)d_in[21];
    const float* m1b  = (const float*)d_in[22];
    const float* m2w  = (const float*)d_in[23];
    const float* m2b  = (const float*)d_in[24];
    const float* g1w  = (const float*)d_in[25];
    const float* g1b  = (const float*)d_in[26];
    const float* g2w  = (const float*)d_in[27];
    const float* g2b  = (const float*)d_in[28];
    const float* opw  = (const float*)d_in[29];
    float* out = (float*)d_out;

    float  *pSESC;
    __half *pTh, *pTA16, *pPW16, *pX116, *pH16, *pH16b, *pQKV16, *pHID16, *pCTX16,
           *pGH16, *pSE16, *pSEH16, *pW16;
    cudaGetSymbolAddress((void**)&pSESC,  g_sesc);
    cudaGetSymbolAddress((void**)&pTh,    g_Th);
    cudaGetSymbolAddress((void**)&pTA16,  g_tA16);
    cudaGetSymbolAddress((void**)&pPW16,  g_pw16);
    cudaGetSymbolAddress((void**)&pX116,  g_x116);
    cudaGetSymbolAddress((void**)&pH16,   g_h16);
    cudaGetSymbolAddress((void**)&pH16b,  g_h16b);
    cudaGetSymbolAddress((void**)&pQKV16, g_qkv16);
    cudaGetSymbolAddress((void**)&pHID16, g_hid16);
    cudaGetSymbolAddress((void**)&pCTX16, g_ctx16);
    cudaGetSymbolAddress((void**)&pGH16,  g_gh16);
    cudaGetSymbolAddress((void**)&pSE16,  g_se16);
    cudaGetSymbolAddress((void**)&pSEH16, g_seh16);
    cudaGetSymbolAddress((void**)&pW16,   g_w16);

    cudaFuncSetAttribute(gemm_hf<0>, cudaFuncAttributeMaxDynamicSharedMemorySize, GEMM_SMEM);
    cudaFuncSetAttribute(gemm_hf<1>, cudaFuncAttributeMaxDynamicSharedMemorySize, GEMM_SMEM);
    cudaFuncSetAttribute(gemm_hf<2>, cudaFuncAttributeMaxDynamicSharedMemorySize, GEMM_SMEM);
    cudaFuncSetAttribute(gemm_hf<3>, cudaFuncAttributeMaxDynamicSharedMemorySize, GEMM_SMEM);
    cudaFuncSetAttribute(gemm_hf<4>, cudaFuncAttributeMaxDynamicSharedMemorySize, GEMM_SMEM);
    cudaFuncSetAttribute(gemm_hf<5>, cudaFuncAttributeMaxDynamicSharedMemorySize, GEMM_SMEM);
    cudaFuncSetAttribute(gemm_hf<6>, cudaFuncAttributeMaxDynamicSharedMemorySize, GEMM_SMEM);

    // 0. weights -> fp16 (main + zero-padded SE)
    cvt_all<<<3712, 256>>>(pw, ipw, aow, f1w, f2w, m1w, m2w, opw, g1w);
    cvt_se<<<512, 256>>>(sew1, sew2);

    // 1. tokens + gating context
    transpose_ctx_k<<<NS, 128>>>(br);
    // 2. gating MLP + softmax
    gemm_hf<1><<<dim3(1,128),256,GEMM_SMEM>>>(pCTX16, pW16+OFF_G1, g1b, nullptr, pGH16, NS, 128, 1024);
    gate2_k<<<NS/8, 256>>>(g2w, g2b);
    // 3. conv expert: pointwise conv
    gemm_hf<0><<<dim3(4,512),256,GEMM_SMEM>>>(pTh, pW16+OFF_PW, nullptr, nullptr, pPW16, RTOT, 512, 512);
    // 4. depthwise (in place) + SE squeeze
    dw_se_k<<<NS, 128>>>(dww);
    // 5. SE MLP (tensor cores, zero-padded)
    gemm_hf<4><<<dim3(1,128),256,GEMM_SMEM>>>(pSE16, pW16+OFF_SE1, nullptr, nullptr, pSEH16, NS, 128, 512);
    gemm_hf<5><<<dim3(4,128),256,GEMM_SMEM>>>(pSEH16, pW16+OFF_SE2, nullptr, nullptr, pSESC, NS, 512, 128);
    // 6. SE scale + GroupNorm + GELU -> x1 (fp16)
    gn_k<<<NS, 256>>>(pSESC, gnw, gnb, pX116);
    // 7. both LNs over Th in one pass (attn -> h16, mlp -> h16b)
    ln2_k<<<RTOT/8, 256>>>(pTh, lnaw, lnab, pH16, mlw, mlb, pH16b, RTOT);
    // 8. attention expert
    gemm_hf<0><<<dim3(12,512),256,GEMM_SMEM>>>(pH16, pW16+OFF_IP, ipb, nullptr, pQKV16, RTOT, 1536, 512);
    attn_k<<<NS, 128>>>(pQKV16, pH16);
    gemm_hf<2><<<dim3(4,512),256,GEMM_SMEM>>>(pH16, pW16+OFF_AO, aob, pTh, pTA16, RTOT, 512, 512);
    ln_k<<<RTOT/8, 256>>>(pTA16, lnfw, lnfb, pH16, RTOT);
    gemm_hf<1><<<dim3(8,512),256,GEMM_SMEM>>>(pH16, pW16+OFF_F1, f1b, nullptr, pHID16, RTOT, 1024, 512);
    gemm_hf<2><<<dim3(4,512),256,GEMM_SMEM>>>(pHID16, pW16+OFF_F2, f2b, pTA16, pTA16, RTOT, 512, 1024);
    // 9. mlp expert (m2 epilogue also does the 3-expert alpha fusion -> h16)
    gemm_hf<1><<<dim3(8,512),256,GEMM_SMEM>>>(pH16b, pW16+OFF_M1, m1b, nullptr, pHID16, RTOT, 1024, 512);
    gemm_hf<6><<<dim3(4,512),256,GEMM_SMEM>>>(pHID16, pW16+OFF_M2, m2b, pTh, pH16, RTOT, 512, 1024);
    // 10. output projection (scatter to (n,o,b))
    gemm_hf<3><<<dim3(4,512),256,GEMM_SMEM>>>(pH16, pW16+OFF_OP, nullptr, nullptr, out, RTOT, 512, 512);
}

// round 16
// speedup vs baseline: 1.1520x; 1.1506x over previous
#include <cuda_runtime.h>
#include <cuda_fp16.h>
#include <math.h>
#include <stdint.h>

// ---------------- problem constants ----------------
#define NS   16384
#define FF   512
#define BBR  4
#define RTOT (NS*BBR)
#define QKVD 1536
#define HIDD 1024
#define GHID 128
#define SEH  64

// ---------------- scratch ----------------
// fp32 (stats only)
__device__ float  g_sesc[NS*FF];       // SE sigmoid scale
__device__ float  g_al  [NS*4];        // alpha
// fp16 (everything else)
__device__ __half g_Th  [RTOT*FF];     // tokens fp16 (residual base, LN input, pw GEMM A)
__device__ __half g_tA16[RTOT*FF];     // attention stream (fp16)
__device__ __half g_pw16[RTOT*FF];     // pw conv out -> depthwise out (in place)
__device__ __half g_x116[RTOT*FF];     // conv expert out (fp16)
__device__ __half g_h16 [RTOT*FF];     // LN-attn out / attn out / fuse out
__device__ __half g_h16b[RTOT*FF];     // LN-mlp out (computed early, used late)
__device__ __half g_qkv16[RTOT*QKVD];
__device__ __half g_hid16[RTOT*HIDD];
__device__ __half g_ctx16[NS*1024];
__device__ __half g_gh16 [NS*GHID];
__device__ __half g_se16 [NS*FF];      // SE squeeze (fp16)
__device__ __half g_seh16[NS*GHID];    // SE hidden, padded to 128

// fp16 weights, concatenated (element offsets); SE weights zero-padded
#define OFF_PW  0
#define OFF_IP  262144
#define OFF_AO  1048576
#define OFF_F1  1310720
#define OFF_F2  1835008
#define OFF_M1  2359296
#define OFF_M2  2883584
#define OFF_OP  3407872
#define OFF_G1  3670016
#define OFF_SE2 3801088            // 512 x 128 (K padded from 64)
#define OFF_SE1 3866624            // 128 x 512 (N padded from 64)
#define WTOT    3932160
__device__ __half g_w16[WTOT];

__device__ __forceinline__ float gelu_f(float x) {
    return 0.5f * x * (1.0f + erff(x * 0.70710678118654752440f));
}
__device__ __forceinline__ uint32_t h2u(float a, float b) {
    __half2 h = __floats2half2_rn(a, b);
    return *reinterpret_cast<uint32_t*>(&h);
}
__device__ __forceinline__ float2 u2f(uint32_t u) {
    __half2 h = *reinterpret_cast<__half2*>(&u);
    return make_float2(__low2float(h), __high2float(h));
}

__device__ __forceinline__ void mma_f16(float* c, const uint32_t* a, const uint32_t* b) {
    asm volatile(
        "mma.sync.aligned.m16n8k16.row.col.f32.f16.f16.f32 "
        "{%0,%1,%2,%3}, {%4,%5,%6,%7}, {%8,%9}, {%0,%1,%2,%3};"
        : "+f"(c[0]), "+f"(c[1]), "+f"(c[2]), "+f"(c[3])
        : "r"(a[0]), "r"(a[1]), "r"(a[2]), "r"(a[3]), "r"(b[0]), "r"(b[1]));
}
#define LDMX4(r0, r1, r2, r3, addr) \
    asm volatile("ldmatrix.sync.aligned.m8n8.x4.shared.b16 {%0,%1,%2,%3}, [%4];" \
                 : "=r"(r0), "=r"(r1), "=r"(r2), "=r"(r3) : "r"(addr))

#define CP16(dst, src) asm volatile("cp.async.cg.shared.global [%0], [%1], 16;" :: "r"(dst), "l"(src))
#define CP_COMMIT()    asm volatile("cp.async.commit_group;" ::: "memory")
#define CP_WAIT2()     asm volatile("cp.async.wait_group 2;" ::: "memory")
#define CP_WAIT1()     asm volatile("cp.async.wait_group 1;" ::: "memory")
#define CP_WAIT0()     asm volatile("cp.async.wait_group 0;" ::: "memory")

// stage geometry: [4 stages][128 rows][80 bytes] per operand (32 halves + 16B pad)
#define STG_WORDS 2560
#define STG_BYTES 10240u
#define W_REGION  10240          // word offset of W region
#define GEMM_SMEM 81920

// ---------------- main weights fp32 -> fp16, one launch ----------------
__global__ void cvt_all(const float* s0, const float* s1, const float* s2,
                        const float* s3, const float* s4, const float* s5,
                        const float* s6, const float* s7, const float* s8)
{
    int i = blockIdx.x * 256 + threadIdx.x;      // float4 index into g_w16
    if (i >= 950272) return;
    const float* s; int base;
    if      (i < 65536)  { s = s0; base = 0; }
    else if (i < 262144) { s = s1; base = 65536; }
    else if (i < 327680) { s = s2; base = 262144; }
    else if (i < 458752) { s = s3; base = 327680; }
    else if (i < 589824) { s = s4; base = 458752; }
    else if (i < 720896) { s = s5; base = 589824; }
    else if (i < 851968) { s = s6; base = 720896; }
    else if (i < 917504) { s = s7; base = 851968; }
    else                 { s = s8; base = 917504; }
    float4 v = ((const float4*)s)[i - base];
    uint2 o;
    o.x = h2u(v.x, v.y);
    o.y = h2u(v.z, v.w);
    ((uint2*)g_w16)[i] = o;
}

// ---------------- SE weights, zero-padded, fp32 -> fp16 ----------------
// se1p [128][512] (rows >= 64 zero), se2p [512][128] (cols >= 64 zero)
__global__ void cvt_se(const float* __restrict__ w1, const float* __restrict__ w2)
{
    int i = blockIdx.x * 256 + threadIdx.x;      // half2 index, 2*65536 total
    if (i < 65536) {
        const int r = i >> 8, c2 = i & 255;      // cols 2*c2, 2*c2+1
        uint32_t o = 0;
        if (r < 64) o = h2u(w1[r*512 + 2*c2], w1[r*512 + 2*c2 + 1]);
        ((uint32_t*)(g_w16 + OFF_SE1))[i] = o;
    } else {
        const int j = i - 65536;
        const int r = j >> 6, c2 = j & 63;
        uint32_t o = 0;
        if (c2 < 32) o = h2u(w2[r*64 + 2*c2], w2[r*64 + 2*c2 + 1]);
        ((uint32_t*)(g_w16 + OFF_SE2))[j] = o;
    }
}

// ---------------- FP16 tensor-core GEMM (4-stage cp.async + ldmatrix) ----------------
// C = epi(A[M,K] @ W[N,K]^T + bias [,+Res]).  256 threads, 8 warps (2x4),
// warp tile 64x32 (4x4 of m16n8k16), block tile 128x128, K chunk 32. K%32==0.
// EPI: 0 none->f16, 1 gelu->f16, 2 +Res(f16)->f16, 3 scatter(n,o,b)->f32,
//      4 relu->f16, 5 sigmoid->f32, 6 expert-fuse->f16
template<int EPI>
__global__ __launch_bounds__(256)
void gemm_hf(const __half* __restrict__ A, const __half* __restrict__ W,
             const float* __restrict__ bias, const __half* __restrict__ Res,
             void* __restrict__ Cv, int M, int N, int K)
{
    extern __shared__ uint32_t sm_[];

    const int bm   = blockIdx.y * 128;
    const int bn   = blockIdx.x * 128;
    const int tid  = threadIdx.x;
    const int wid  = tid >> 5;
    const int lane = tid & 31;
    const int wm   = wid & 1;
    const int wn   = wid >> 1;
    const int grp  = lane >> 2;
    const int tq   = lane & 3;

    // loaders: 2 threads per row, each covers 16 halves (two 16B chunks)
    const int lrow = tid >> 1;
    const int lh   = (tid & 1) * 16;
    const __half* aSrc = A + (size_t)(bm + lrow) * K + lh;
    const __half* wSrc = W + (size_t)(bn + lrow) * K + lh;
    uint32_t sbase;
    asm("{ .reg .u64 t; cvta.to.shared.u64 t, %1; cvt.u32.u64 %0, t; }" : "=r"(sbase) : "l"(sm_));
    const uint32_t dstA = sbase + (uint32_t)(lrow * 80 + lh * 2);
    const uint32_t dstW = dstA + W_REGION * 4;

    // ldmatrix per-thread base addresses (stage 0)
    const uint32_t lmA = sbase + (uint32_t)((wm * 64 + (lane & 15)) * 80 + (lane >> 4) * 16);
    const uint32_t lmB = sbase + W_REGION * 4 +
        (uint32_t)((wn * 32 + (lane >> 4) * 8 + (lane & 7)) * 80 + ((lane >> 3) & 1) * 16);

    float acc[4][4][4];
#pragma unroll
    for (int i = 0; i < 4; i++)
#pragma unroll
        for (int j = 0; j < 4; j++)
#pragma unroll
            for (int q = 0; q < 4; q++) acc[i][j][q] = 0.f;

    const int steps = K >> 5;

    auto issue = [&](int s) {
        const uint32_t so = (uint32_t)(s & 3) * STG_BYTES;
        const __half* a = aSrc + s * 32;
        const __half* w = wSrc + s * 32;
        CP16(dstA + so, a);  CP16(dstA + so + 16, a + 8);
        CP16(dstW + so, w);  CP16(dstW + so + 16, w + 8);
        CP_COMMIT();
    };

    issue(0);
    if (steps > 1) issue(1);
    if (steps > 2) issue(2);

    for (int i = 0; i < steps; i++) {
        const int pend = steps - 1 - i;
        if (pend >= 2) { CP_WAIT2(); }
        else if (pend == 1) { CP_WAIT1(); }
        else { CP_WAIT0(); }
        __syncthreads();

        const uint32_t so = (uint32_t)(i & 3) * STG_BYTES;
#pragma unroll
        for (int sub = 0; sub < 2; sub++) {
            const uint32_t ko = so + (uint32_t)sub * 32;
            uint32_t af[4][4], bf[4][2];
#pragma unroll
            for (int mt = 0; mt < 4; mt++)
                LDMX4(af[mt][0], af[mt][1], af[mt][2], af[mt][3],
                      lmA + ko + (uint32_t)(mt * 16 * 80));
#pragma unroll
            for (int p = 0; p < 2; p++)
                LDMX4(bf[p*2][0], bf[p*2][1], bf[p*2+1][0], bf[p*2+1][1],
                      lmB + ko + (uint32_t)(p * 16 * 80));
#pragma unroll
            for (int mt = 0; mt < 4; mt++)
#pragma unroll
                for (int nt = 0; nt < 4; nt++)
                    mma_f16(acc[mt][nt], af[mt], bf[nt]);
        }

        if (i + 3 < steps) issue(i + 3);   // writes slot (i-1)&3: safe post-barrier
    }

    // ---------------- epilogue ----------------
#pragma unroll
    for (int mt = 0; mt < 4; mt++) {
        const int rbase = bm + wm * 64 + mt * 16 + grp;
#pragma unroll
        for (int nt = 0; nt < 4; nt++) {
            const int col = bn + wn * 32 + nt * 8 + tq * 2;
#pragma unroll
            for (int half = 0; half < 2; half++) {
                const int row = rbase + half * 8;
                float x = acc[mt][nt][half * 2 + 0];
                float y = acc[mt][nt][half * 2 + 1];
                if (bias) { x += bias[col]; y += bias[col + 1]; }
                if (EPI == 0) {
                    *(uint32_t*)&((__half*)Cv)[(size_t)row * N + col] = h2u(x, y);
                } else if (EPI == 1) {
                    *(uint32_t*)&((__half*)Cv)[(size_t)row * N + col] = h2u(gelu_f(x), gelu_f(y));
                } else if (EPI == 2) {
                    const size_t off = (size_t)row * N + col;
                    float2 rv = u2f(*(const uint32_t*)&Res[off]);
                    *(uint32_t*)&((__half*)Cv)[off] = h2u(x + rv.x, y + rv.y);
                } else if (EPI == 3) {
                    float* base = (float*)Cv + (size_t)(row >> 2) * 2048 + (row & 3);
                    base[col * 4]       = x;
                    base[(col + 1) * 4] = y;
                } else if (EPI == 4) {
                    *(uint32_t*)&((__half*)Cv)[(size_t)row * N + col] =
                        h2u(fmaxf(x, 0.f), fmaxf(y, 0.f));
                } else if (EPI == 5) {
                    *(float2*)&((float*)Cv)[(size_t)row * N + col] =
                        make_float2(1.f / (1.f + expf(-x)), 1.f / (1.f + expf(-y)));
                } else if (EPI == 6) {
                    // t3 = acc + bias + T(f16);  out = a0*x1 + a1*tA + a2*t3  (fp16)
                    const size_t off = (size_t)row * N + col;
                    float2 rv = u2f(*(const uint32_t*)&Res[off]);
                    x += rv.x; y += rv.y;
                    const int n = row >> 2;
                    const float a0 = g_al[n*4+0], a1 = g_al[n*4+1], a2 = g_al[n*4+2];
                    float2 u = u2f(*(const uint32_t*)&g_x116[off]);
                    float2 v = u2f(*(const uint32_t*)&g_tA16[off]);
                    float fx = a0*u.x + a1*v.x + a2*x;
                    float fy = a0*u.y + a1*v.y + a2*y;
                    *(uint32_t*)&((__half*)Cv)[off] = h2u(fx, fy);
                }
            }
        }
    }
}

// ---------------- transpose: fp16 tokens + fp16 gating ctx ----------------
__global__ void transpose_ctx_k(const float* __restrict__ br)
{
    const int n   = blockIdx.x;
    const int f0  = threadIdx.x * 4;   // 128 threads
    const float* src = br + (size_t)n * 2048;
    float4 r0 = *(const float4*)&src[(f0+0)*4];
    float4 r1 = *(const float4*)&src[(f0+1)*4];
    float4 r2 = *(const float4*)&src[(f0+2)*4];
    float4 r3 = *(const float4*)&src[(f0+3)*4];
    __half* th = g_Th + (size_t)n * 2048;
    *(uint2*)&th[0*512 + f0] = make_uint2(h2u(r0.x, r1.x), h2u(r2.x, r3.x));
    *(uint2*)&th[1*512 + f0] = make_uint2(h2u(r0.y, r1.y), h2u(r2.y, r3.y));
    *(uint2*)&th[2*512 + f0] = make_uint2(h2u(r0.z, r1.z), h2u(r2.z, r3.z));
    *(uint2*)&th[3*512 + f0] = make_uint2(h2u(r0.w, r1.w), h2u(r2.w, r3.w));
    __half* cx = g_ctx16 + (size_t)n * 1024;
    float m0 = 0.25f*(r0.x+r0.y+r0.z+r0.w), m1 = 0.25f*(r1.x+r1.y+r1.z+r1.w);
    float m2 = 0.25f*(r2.x+r2.y+r2.z+r2.w), m3 = 0.25f*(r3.x+r3.y+r3.z+r3.w);
    float x0 = fmaxf(fmaxf(r0.x,r0.y),fmaxf(r0.z,r0.w));
    float x1 = fmaxf(fmaxf(r1.x,r1.y),fmaxf(r1.z,r1.w));
    float x2 = fmaxf(fmaxf(r2.x,r2.y),fmaxf(r2.z,r2.w));
    float x3 = fmaxf(fmaxf(r3.x,r3.y),fmaxf(r3.z,r3.w));
    *(uint2*)&cx[f0]       = make_uint2(h2u(m0, m1), h2u(m2, m3));
    *(uint2*)&cx[512 + f0] = make_uint2(h2u(x0, x1), h2u(x2, x3));
}

// ---------------- LayerNorm (warp per row): fp16 in, fp16 out ----------------
__global__ void ln_k(const __half* __restrict__ X, const float* __restrict__ w,
                     const float* __restrict__ b, __half* __restrict__ Y, int rows)
{
    const int gw   = (int)((blockIdx.x * (size_t)blockDim.x + threadIdx.x) >> 5);
    const int lane = threadIdx.x & 31;
    if (gw >= rows) return;
    const __half* x = X + (size_t)gw * FF;
    float v[16];
    float s = 0.f, sq = 0.f;
#pragma unroll
    for (int i = 0; i < 4; i++) {
        uint2 u = *(const uint2*)&x[lane*4 + i*128];
        float2 ab = u2f(u.x), cd = u2f(u.y);
        v[i*4+0] = ab.x; v[i*4+1] = ab.y; v[i*4+2] = cd.x; v[i*4+3] = cd.y;
        s  += ab.x + ab.y + cd.x + cd.y;
        sq += ab.x*ab.x + ab.y*ab.y + cd.x*cd.x + cd.y*cd.y;
    }
#pragma unroll
    for (int o = 16; o > 0; o >>= 1) {
        s  += __shfl_xor_sync(~0u, s,  o);
        sq += __shfl_xor_sync(~0u, sq, o);
    }
    const float m   = s  * (1.f/FF);
    const float var = sq * (1.f/FF) - m*m;
    const float rs  = rsqrtf(var + 1e-5f);
    __half* y = Y + (size_t)gw * FF;
#pragma unroll
    for (int i = 0; i < 4; i++) {
        const int f = lane*4 + i*128;
        float4 wv = *(const float4*)&w[f];
        float4 bv = *(const float4*)&b[f];
        float o0 = (v[i*4+0] - m)*rs*wv.x + bv.x;
        float o1 = (v[i*4+1] - m)*rs*wv.y + bv.y;
        float o2 = (v[i*4+2] - m)*rs*wv.z + bv.z;
        float o3 = (v[i*4+3] - m)*rs*wv.w + bv.w;
        *(uint2*)&y[f] = make_uint2(h2u(o0, o1), h2u(o2, o3));
    }
}

// ---------------- dual LayerNorm over g_Th: one stats pass, two outputs ----------
__global__ void ln2_k(const __half* __restrict__ X,
                      const float* __restrict__ w1, const float* __restrict__ b1,
                      __half* __restrict__ Y1,
                      const float* __restrict__ w2, const float* __restrict__ b2,
                      __half* __restrict__ Y2, int rows)
{
    const int gw   = (int)((blockIdx.x * (size_t)blockDim.x + threadIdx.x) >> 5);
    const int lane = threadIdx.x & 31;
    if (gw >= rows) return;
    const __half* x = X + (size_t)gw * FF;
    float v[16];
    float s = 0.f, sq = 0.f;
#pragma unroll
    for (int i = 0; i < 4; i++) {
        uint2 u = *(const uint2*)&x[lane*4 + i*128];
        float2 ab = u2f(u.x), cd = u2f(u.y);
        v[i*4+0] = ab.x; v[i*4+1] = ab.y; v[i*4+2] = cd.x; v[i*4+3] = cd.y;
        s  += ab.x + ab.y + cd.x + cd.y;
        sq += ab.x*ab.x + ab.y*ab.y + cd.x*cd.x + cd.y*cd.y;
    }
#pragma unroll
    for (int o = 16; o > 0; o >>= 1) {
        s  += __shfl_xor_sync(~0u, s,  o);
        sq += __shfl_xor_sync(~0u, sq, o);
    }
    const float m   = s  * (1.f/FF);
    const float var = sq * (1.f/FF) - m*m;
    const float rs  = rsqrtf(var + 1e-5f);
    __half* y1 = Y1 + (size_t)gw * FF;
    __half* y2 = Y2 + (size_t)gw * FF;
#pragma unroll
    for (int i = 0; i < 4; i++) {
        const int f = lane*4 + i*128;
        const float nx = (v[i*4+0] - m)*rs, ny = (v[i*4+1] - m)*rs;
        const float nz = (v[i*4+2] - m)*rs, nw = (v[i*4+3] - m)*rs;
        float4 wa = *(const float4*)&w1[f];
        float4 ba = *(const float4*)&b1[f];
        *(uint2*)&y1[f] = make_uint2(h2u(nx*wa.x + ba.x, ny*wa.y + ba.y),
                                     h2u(nz*wa.z + ba.z, nw*wa.w + ba.w));
        float4 wb = *(const float4*)&w2[f];
        float4 bb = *(const float4*)&b2[f];
        *(uint2*)&y2[f] = make_uint2(h2u(nx*wb.x + bb.x, ny*wb.y + bb.y),
                                     h2u(nz*wb.z + bb.z, nw*wb.w + bb.w));
    }
}

// ---------------- depthwise conv IN PLACE on g_pw16 + SE squeeze (fp16) ----------
__global__ void dw_se_k(const float* __restrict__ dw)
{
    const int n  = blockIdx.x;
    const int f0 = threadIdx.x * 4;
    __half* p = g_pw16 + (size_t)n * 2048;
    float xb[4][4];
#pragma unroll
    for (int b = 0; b < 4; b++) {
        uint2 u = *(const uint2*)&p[b*512 + f0];
        float2 ab = u2f(u.x), cd = u2f(u.y);
        xb[b][0] = ab.x; xb[b][1] = ab.y; xb[b][2] = cd.x; xb[b][3] = cd.y;
    }
    float w0[4], w1[4], w2[4];
#pragma unroll
    for (int j = 0; j < 4; j++) {
        w0[j] = dw[(f0+j)*3 + 0];
        w1[j] = dw[(f0+j)*3 + 1];
        w2[j] = dw[(f0+j)*3 + 2];
    }
    float yb[4][4], sm[4];
#pragma unroll
    for (int j = 0; j < 4; j++) {
        yb[0][j] =                    w1[j]*xb[0][j] + w2[j]*xb[1][j];
        yb[1][j] = w0[j]*xb[0][j] + w1[j]*xb[1][j] + w2[j]*xb[2][j];
        yb[2][j] = w0[j]*xb[1][j] + w1[j]*xb[2][j] + w2[j]*xb[3][j];
        yb[3][j] = w0[j]*xb[2][j] + w1[j]*xb[3][j];
        sm[j] = 0.25f*(yb[0][j] + yb[1][j] + yb[2][j] + yb[3][j]);
    }
#pragma unroll
    for (int b = 0; b < 4; b++)
        *(uint2*)&p[b*512 + f0] = make_uint2(h2u(yb[b][0], yb[b][1]), h2u(yb[b][2], yb[b][3]));
    *(uint2*)&g_se16[(size_t)n*512 + f0] = make_uint2(h2u(sm[0], sm[1]), h2u(sm[2], sm[3]));
}

// ---------------- SE-scale + GroupNorm + GELU (fp16 in, fp16 out) ----------------
__global__ void gn_k(const float* __restrict__ SC,
                     const float* __restrict__ gw, const float* __restrict__ gb,
                     __half* __restrict__ Y)
{
    __shared__ float ws[8], wq[8], stats[2];
    const int n = blockIdx.x, tid = threadIdx.x;   // 256 threads, 4 half2 each
    const __half* x = g_pw16 + (size_t)n * 2048;
    const float* sc = SC + (size_t)n * 512;
    float v[8];
    float s = 0.f, sq = 0.f;
#pragma unroll
    for (int i = 0; i < 4; i++) {
        const int e2 = tid + i*256;          // half2 index, element e = e2*2
        const int e  = e2 * 2;
        float2 h = u2f(*(const uint32_t*)&x[e]);
        const int f = e & 511;
        float a = h.x * sc[f];
        float b = h.y * sc[f + 1];
        v[i*2]   = a; v[i*2+1] = b;
        s += a + b; sq += a*a + b*b;
    }
#pragma unroll
    for (int o = 16; o > 0; o >>= 1) {
        s  += __shfl_xor_sync(~0u, s,  o);
        sq += __shfl_xor_sync(~0u, sq, o);
    }
    if ((tid & 31) == 0) { ws[tid >> 5] = s; wq[tid >> 5] = sq; }
    __syncthreads();
    if (tid == 0) {
        float S = 0.f, Q = 0.f;
#pragma unroll
        for (int i = 0; i < 8; i++) { S += ws[i]; Q += wq[i]; }
        const float m = S * (1.f/2048.f);
        stats[0] = m;
        stats[1] = rsqrtf(Q * (1.f/2048.f) - m*m + 1e-5f);
    }
    __syncthreads();
    const float m = stats[0], r = stats[1];
    __half* y = Y + (size_t)n * 2048;
#pragma unroll
    for (int i = 0; i < 4; i++) {
        const int e2 = tid + i*256;
        const int e  = e2 * 2;
        const int f  = e & 511;
        float a = gelu_f((v[i*2]   - m) * r * gw[f]     + gb[f]);
        float b = gelu_f((v[i*2+1] - m) * r * gw[f + 1] + gb[f + 1]);
        *(uint32_t*)&y[e] = h2u(a, b);
    }
}

// ---------------- attention core (fp16 in/out, fp32 math) ----------------
__global__ void attn_k(const __half* __restrict__ QKV, __half* __restrict__ AO)
{
    const int n     = blockIdx.x;
    const int wid   = threadIdx.x >> 5;
    const int lane  = threadIdx.x & 31;
    const int dbase = wid*128 + lane*4;
    const __half* base = QKV + (size_t)n * 4 * 1536;
    float q[4][4], k[4][4], vv[4][4];
    const float sc = 0.08838834764831845f;
#pragma unroll
    for (int i = 0; i < 4; i++) {
        uint2 uq = *(const uint2*)&base[i*1536 +        dbase];
        uint2 uk = *(const uint2*)&base[i*1536 +  512 + dbase];
        uint2 uv = *(const uint2*)&base[i*1536 + 1024 + dbase];
        float2 q0 = u2f(uq.x), q1 = u2f(uq.y);
        float2 k0 = u2f(uk.x), k1 = u2f(uk.y);
        float2 v0 = u2f(uv.x), v1 = u2f(uv.y);
        q[i][0] = q0.x*sc; q[i][1] = q0.y*sc; q[i][2] = q1.x*sc; q[i][3] = q1.y*sc;
        k[i][0] = k0.x; k[i][1] = k0.y; k[i][2] = k1.x; k[i][3] = k1.y;
        vv[i][0] = v0.x; vv[i][1] = v0.y; vv[i][2] = v1.x; vv[i][3] = v1.y;
    }
    float p[4][4];
#pragma unroll
    for (int i = 0; i < 4; i++)
#pragma unroll
        for (int j = 0; j < 4; j++) {
            float d = q[i][0]*k[j][0] + q[i][1]*k[j][1] + q[i][2]*k[j][2] + q[i][3]*k[j][3];
#pragma unroll
            for (int o = 16; o > 0; o >>= 1) d += __shfl_xor_sync(~0u, d, o);
            p[i][j] = d;
        }
    __half* ao = AO + (size_t)n * 4 * 512;
#pragma unroll
    for (int i = 0; i < 4; i++) {
        const float m  = fmaxf(fmaxf(p[i][0], p[i][1]), fmaxf(p[i][2], p[i][3]));
        const float e0 = expf(p[i][0]-m), e1 = expf(p[i][1]-m);
        const float e2 = expf(p[i][2]-m), e3 = expf(p[i][3]-m);
        const float inv = 1.f / (e0+e1+e2+e3);
        float o0 = (e0*vv[0][0] + e1*vv[1][0] + e2*vv[2][0] + e3*vv[3][0]) * inv;
        float o1 = (e0*vv[0][1] + e1*vv[1][1] + e2*vv[2][1] + e3*vv[3][1]) * inv;
        float o2 = (e0*vv[0][2] + e1*vv[1][2] + e2*vv[2][2] + e3*vv[3][2]) * inv;
        float o3 = (e0*vv[0][3] + e1*vv[1][3] + e2*vv[2][3] + e3*vv[3][3]) * inv;
        *(uint2*)&ao[i*512 + dbase] = make_uint2(h2u(o0, o1), h2u(o2, o3));
    }
}

// ---------------- gate logits + softmax (fp16 hidden) ----------------
__global__ void gate2_k(const float* __restrict__ w2, const float* __restrict__ b2)
{
    const int n    = (int)((blockIdx.x * (size_t)blockDim.x + threadIdx.x) >> 5);
    const int lane = threadIdx.x & 31;
    if (n >= NS) return;
    const __half* h = g_gh16 + (size_t)n * 128;
    float lg[3];
#pragma unroll
    for (int e = 0; e < 3; e++) {
        float ps = __half2float(h[lane])      * w2[e*128 + lane]
                 + __half2float(h[lane + 32]) * w2[e*128 + lane + 32]
                 + __half2float(h[lane + 64]) * w2[e*128 + lane + 64]
                 + __half2float(h[lane + 96]) * w2[e*128 + lane + 96];
#pragma unroll
        for (int o = 16; o > 0; o >>= 1) ps += __shfl_xor_sync(~0u, ps, o);
        lg[e] = ps + b2[e];
    }
    if (lane == 0) {
        const float m  = fmaxf(lg[0], fmaxf(lg[1], lg[2]));
        const float e0 = expf(lg[0]-m), e1 = expf(lg[1]-m), e2 = expf(lg[2]-m);
        const float inv = 1.f / (e0+e1+e2);
        g_al[n*4+0] = e0*inv; g_al[n*4+1] = e1*inv; g_al[n*4+2] = e2*inv;
    }
}

// ---------------- launch ----------------
extern "C" void kernel_launch(void* const* d_in, const int* in_sizes, int n_in,
                              void* d_out, int out_size)
{
    (void)in_sizes; (void)n_in; (void)out_size;
    const float* br   = (const float*)d_in[0];
    const float* pw   = (const float*)d_in[1];
    const float* dww  = (const float*)d_in[2];
    const float* gnw  = (const float*)d_in[3];
    const float* gnb  = (const float*)d_in[4];
    const float* sew1 = (const float*)d_in[5];
    const float* sew2 = (const float*)d_in[6];
    const float* lnaw = (const float*)d_in[7];
    const float* lnab = (const float*)d_in[8];
    const float* ipw  = (const float*)d_in[9];
    const float* ipb  = (const float*)d_in[10];
    const float* aow  = (const float*)d_in[11];
    const float* aob  = (const float*)d_in[12];
    const float* lnfw = (const float*)d_in[13];
    const float* lnfb = (const float*)d_in[14];
    const float* f1w  = (const float*)d_in[15];
    const float* f1b  = (const float*)d_in[16];
    const float* f2w  = (const float*)d_in[17];
    const float* f2b  = (const float*)d_in[18];
    const float* mlw  = (const float*)d_in[19];
    const float* mlb  = (const float*)d_in[20];
    const float* m1w  = (const float*)d_in[21];
    const float* m1b  = (const float*)d_in[22];
    const float* m2w  = (const float*)d_in[23];
    const float* m2b  = (const float*)d_in[24];
    const float* g1w  = (const float*)d_in[25];
    const float* g1b  = (const float*)d_in[26];
    const float* g2w  = (const float*)d_in[27];
    const float* g2b  = (const float*)d_in[28];
    const float* opw  = (const float*)d_in[29];
    float* out = (float*)d_out;

    float  *pSESC;
    __half *pTh, *pTA16, *pPW16, *pX116, *pH16, *pH16b, *pQKV16, *pHID16, *pCTX16,
           *pGH16, *pSE16, *pSEH16, *pW16;
    cudaGetSymbolAddress((void**)&pSESC,  g_sesc);
    cudaGetSymbolAddress((void**)&pTh,    g_Th);
    cudaGetSymbolAddress((void**)&pTA16,  g_tA16);
    cudaGetSymbolAddress((void**)&pPW16,  g_pw16);
    cudaGetSymbolAddress((void**)&pX116,  g_x116);
    cudaGetSymbolAddress((void**)&pH16,   g_h16);
    cudaGetSymbolAddress((void**)&pH16b,  g_h16b);
    cudaGetSymbolAddress((void**)&pQKV16, g_qkv16);
    cudaGetSymbolAddress((void**)&pHID16, g_hid16);
    cudaGetSymbolAddress((void**)&pCTX16, g_ctx16);
    cudaGetSymbolAddress((void**)&pGH16,  g_gh16);
    cudaGetSymbolAddress((void**)&pSE16,  g_se16);
    cudaGetSymbolAddress((void**)&pSEH16, g_seh16);
    cudaGetSymbolAddress((void**)&pW16,   g_w16);

    cudaFuncSetAttribute(gemm_hf<0>, cudaFuncAttributeMaxDynamicSharedMemorySize, GEMM_SMEM);
    cudaFuncSetAttribute(gemm_hf<1>, cudaFuncAttributeMaxDynamicSharedMemorySize, GEMM_SMEM);
    cudaFuncSetAttribute(gemm_hf<2>, cudaFuncAttributeMaxDynamicSharedMemorySize, GEMM_SMEM);
    cudaFuncSetAttribute(gemm_hf<3>, cudaFuncAttributeMaxDynamicSharedMemorySize, GEMM_SMEM);
    cudaFuncSetAttribute(gemm_hf<4>, cudaFuncAttributeMaxDynamicSharedMemorySize, GEMM_SMEM);
    cudaFuncSetAttribute(gemm_hf<5>, cudaFuncAttributeMaxDynamicSharedMemorySize, GEMM_SMEM);
    cudaFuncSetAttribute(gemm_hf<6>, cudaFuncAttributeMaxDynamicSharedMemorySize, GEMM_SMEM);

    // 0. weights -> fp16 (main + zero-padded SE)
    cvt_all<<<3712, 256>>>(pw, ipw, aow, f1w, f2w, m1w, m2w, opw, g1w);
    cvt_se<<<512, 256>>>(sew1, sew2);

    // 1. tokens + gating context
    transpose_ctx_k<<<NS, 128>>>(br);
    // 2. gating MLP + softmax
    gemm_hf<1><<<dim3(1,128),256,GEMM_SMEM>>>(pCTX16, pW16+OFF_G1, g1b, nullptr, pGH16, NS, 128, 1024);
    gate2_k<<<NS/8, 256>>>(g2w, g2b);
    // 3. conv expert: pointwise conv
    gemm_hf<0><<<dim3(4,512),256,GEMM_SMEM>>>(pTh, pW16+OFF_PW, nullptr, nullptr, pPW16, RTOT, 512, 512);
    // 4. depthwise (in place) + SE squeeze
    dw_se_k<<<NS, 128>>>(dww);
    // 5. SE MLP (tensor cores, zero-padded)
    gemm_hf<4><<<dim3(1,128),256,GEMM_SMEM>>>(pSE16, pW16+OFF_SE1, nullptr, nullptr, pSEH16, NS, 128, 512);
    gemm_hf<5><<<dim3(4,128),256,GEMM_SMEM>>>(pSEH16, pW16+OFF_SE2, nullptr, nullptr, pSESC, NS, 512, 128);
    // 6. SE scale + GroupNorm + GELU -> x1 (fp16)
    gn_k<<<NS, 256>>>(pSESC, gnw, gnb, pX116);
    // 7. both LNs over Th in one pass (attn -> h16, mlp -> h16b)
    ln2_k<<<RTOT/8, 256>>>(pTh, lnaw, lnab, pH16, mlw, mlb, pH16b, RTOT);
    // 8. attention expert
    gemm_hf<0><<<dim3(12,512),256,GEMM_SMEM>>>(pH16, pW16+OFF_IP, ipb, nullptr, pQKV16, RTOT, 1536, 512);
    attn_k<<<NS, 128>>>(pQKV16, pH16);
    gemm_hf<2><<<dim3(4,512),256,GEMM_SMEM>>>(pH16, pW16+OFF_AO, aob, pTh, pTA16, RTOT, 512, 512);
    ln_k<<<RTOT/8, 256>>>(pTA16, lnfw, lnfb, pH16, RTOT);
    gemm_hf<1><<<dim3(8,512),256,GEMM_SMEM>>>(pH16, pW16+OFF_F1, f1b, nullptr, pHID16, RTOT, 1024, 512);
    gemm_hf<2><<<dim3(4,512),256,GEMM_SMEM>>>(pHID16, pW16+OFF_F2, f2b, pTA16, pTA16, RTOT, 512, 1024);
    // 9. mlp expert (m2 epilogue also does the 3-expert alpha fusion -> h16)
    gemm_hf<1><<<dim3(8,512),256,GEMM_SMEM>>>(pH16b, pW16+OFF_M1, m1b, nullptr, pHID16, RTOT, 1024, 512);
    gemm_hf<6><<<dim3(4,512),256,GEMM_SMEM>>>(pHID16, pW16+OFF_M2, m2b, pTh, pH16, RTOT, 512, 1024);
    // 10. output projection (scatter to (n,o,b))
    gemm_hf<3><<<dim3(4,512),256,GEMM_SMEM>>>(pH16, pW16+OFF_OP, nullptr, nullptr, out, RTOT, 512, 512);
}